// round 13
// baseline (speedup 1.0000x reference)
#include <cuda_runtime.h>

#define NRELS 19
#define CPAD  20
#define DIM   32
#define MAXN  100000
#define MAXE  1600000

typedef unsigned int u32;

// ---------------- static scratch (zero-init; each consumer kernel resets
// what it read, so every graph replay starts pristine) ----------------------
static __device__ int4   g_cnt4[MAXN * (CPAD / 4)];   // (node,rel) counts
static __device__ float4 g_h14[MAXN * (DIM / 4)];     // layer-1 activations
static __device__ float4 g_h2[MAXN * (DIM / 4)];      // layer-2 accumulator (perm cols)
static __device__ int2   g_edata[MAXE];               // relation-bucketed (src,dst)
static __device__ int    g_relHist[NRELS];
static __device__ int    g_relCur[NRELS];

// ---------------- helpers ----------------
__device__ __forceinline__ void red4(float* p, float a, float b, float c, float d) {
    asm volatile("red.global.add.v4.f32 [%0], {%1, %2, %3, %4};"
                 :: "l"(p), "f"(a), "f"(b), "f"(c), "f"(d) : "memory");
}
__device__ __forceinline__ u32 smem_u32(const void* p) {
    return (u32)__cvta_generic_to_shared(p);
}
__device__ __forceinline__ void cp_async16(u32 dst, const void* src, int srcsize) {
    asm volatile("cp.async.cg.shared.global [%0], [%1], 16, %2;"
                 :: "r"(dst), "l"(src), "r"(srcsize));
}
__device__ __forceinline__ void cp_commit() { asm volatile("cp.async.commit_group;"); }
__device__ __forceinline__ void cp_wait2()  { asm volatile("cp.async.wait_group 2;"); }
__device__ __forceinline__ void cp_wait0()  { asm volatile("cp.async.wait_group 0;"); }
// pack {lo, hi} floats into bf16x2 (element0 = lo)
__device__ __forceinline__ u32 bf16x2(float lo, float hi) {
    u32 r; asm("cvt.rn.bf16x2.f32 %0, %1, %2;" : "=r"(r) : "f"(hi), "f"(lo)); return r;
}
// residual of a float2 after removing its bf16x2 hi part
__device__ __forceinline__ u32 bf16x2_lo(float x, float y, u32 hi) {
    float lx = x - __uint_as_float(hi << 16);
    float ly = y - __uint_as_float(hi & 0xFFFF0000u);
    return bf16x2(lx, ly);
}
// m16n8k16 bf16 MMA, fp32 accumulate in place.
__device__ __forceinline__ void mma_bf16(float& c0, float& c1, float& c2, float& c3,
                                         u32 a0, u32 a1, u32 a2, u32 a3,
                                         u32 b0, u32 b1) {
    asm volatile("mma.sync.aligned.m16n8k16.row.col.f32.bf16.bf16.f32 "
                 "{%0,%1,%2,%3}, {%4,%5,%6,%7}, {%8,%9}, {%0,%1,%2,%3};"
                 : "+f"(c0), "+f"(c1), "+f"(c2), "+f"(c3)
                 : "r"(a0), "r"(a1), "r"(a2), "r"(a3), "r"(b0), "r"(b1));
}

// ---------------- kernels (order: hist, scatter, layer1, LAYER2, final) ----

__global__ void k_hist(const int* __restrict__ dst, const int* __restrict__ et, int E) {
    __shared__ int sh[NRELS];
    if (threadIdx.x < NRELS) sh[threadIdx.x] = 0;
    __syncthreads();
    int* cnt = (int*)g_cnt4;
    int e0 = (blockIdx.x * blockDim.x + threadIdx.x) * 4;
    if (e0 + 3 < E) {
        int4 d4 = *(const int4*)&dst[e0];
        int4 r4 = *(const int4*)&et[e0];
        atomicAdd(&cnt[d4.x * CPAD + r4.x], 1);
        atomicAdd(&cnt[d4.y * CPAD + r4.y], 1);
        atomicAdd(&cnt[d4.z * CPAD + r4.z], 1);
        atomicAdd(&cnt[d4.w * CPAD + r4.w], 1);
        atomicAdd(&sh[r4.x], 1); atomicAdd(&sh[r4.y], 1);
        atomicAdd(&sh[r4.z], 1); atomicAdd(&sh[r4.w], 1);
    } else {
        for (int e = e0; e < E; e++) {
            int r = et[e];
            atomicAdd(&cnt[dst[e] * CPAD + r], 1);
            atomicAdd(&sh[r], 1);
        }
    }
    __syncthreads();
    if (threadIdx.x < NRELS) atomicAdd(&g_relHist[threadIdx.x], sh[threadIdx.x]);
}

__global__ void k_scatter(const int* __restrict__ src, const int* __restrict__ dst,
                          const int* __restrict__ et, int E) {
    __shared__ int sOff[NRELS];
    __shared__ int shCnt[NRELS];
    __shared__ int shBase[NRELS];
    int t = threadIdx.x;
    if (t < NRELS) {
        shCnt[t] = 0;
        int s = 0;
#pragma unroll
        for (int q = 0; q < NRELS; q++) {
            if (q == t) sOff[t] = s;
            s += g_relHist[q];
        }
    }
    __syncthreads();
    int e0 = (blockIdx.x * blockDim.x + t) * 4;
    int r[4], s[4], d[4], lp[4];
    int cnt = 0;
    if (e0 + 3 < E) {
        int4 s4 = *(const int4*)&src[e0];
        int4 d4 = *(const int4*)&dst[e0];
        int4 r4 = *(const int4*)&et[e0];
        s[0]=s4.x; s[1]=s4.y; s[2]=s4.z; s[3]=s4.w;
        d[0]=d4.x; d[1]=d4.y; d[2]=d4.z; d[3]=d4.w;
        r[0]=r4.x; r[1]=r4.y; r[2]=r4.z; r[3]=r4.w;
        cnt = 4;
    } else {
        for (int e = e0; e < E; e++) {
            s[cnt]=src[e]; d[cnt]=dst[e]; r[cnt]=et[e]; cnt++;
        }
    }
    for (int k = 0; k < cnt; k++) lp[k] = atomicAdd(&shCnt[r[k]], 1);
    __syncthreads();
    if (t < NRELS) shBase[t] = sOff[t] + atomicAdd(&g_relCur[t], shCnt[t]);
    __syncthreads();
    for (int k = 0; k < cnt; k++)
        g_edata[shBase[r[k]] + lp[k]] = make_int2(s[k], d[k]);
}

// Layer 1; also RESETS cnt rows to zero after reading.
__global__ void k_layer1(const float* __restrict__ W1, const float* __restrict__ b1, int N) {
    __shared__ float sW[NRELS * DIM];
    __shared__ float sb[DIM];
    int t = threadIdx.x;
    for (int i = t; i < NRELS * DIM; i += blockDim.x) sW[i] = W1[i];
    if (t < DIM) sb[t] = b1[t];
    __syncthreads();
    int lane = t & 31;
    int wpb = blockDim.x >> 5;
    float* h1 = (float*)g_h14;
    for (int v = blockIdx.x * wpb + (t >> 5); v < N; v += gridDim.x * wpb) {
        int4* crow = &g_cnt4[v * (CPAD / 4)];
        int c[CPAD];
#pragma unroll
        for (int q = 0; q < CPAD / 4; q++) {
            int4 cc = __ldg(&crow[q]);
            c[q * 4 + 0] = cc.x; c[q * 4 + 1] = cc.y;
            c[q * 4 + 2] = cc.z; c[q * 4 + 3] = cc.w;
        }
        float acc = sb[lane];
#pragma unroll
        for (int r = 0; r < NRELS; r++)
            acc += (float)c[r] * sW[r * DIM + lane];
        h1[v * DIM + lane] = fmaxf(acc, 0.0f);
        if (lane < CPAD / 4) crow[lane] = make_int4(0, 0, 0, 0);
    }
}

// Layer 2 (hot): bf16 tensor tiles, 16 edges per tile per warp:
//   D[16 x 32] += A[16 x 32] (gathered h1 rows) @ W2[rel] (32 x 32)
// mma.m16n8k16.bf16, 2x2 hi/lo split, 3 terms.  This round:
//   - 3-stage cp.async pipeline (3 smem buffers, wait_group 2): gather for
//     tile c+32 is in flight while computing tile c -> L2 latency fully hidden
//   - occupancy 6 blocks/SM (85-reg budget; live-reg audit ~65 at hot point)
//   - C scatter unchanged: perm cols, 4 red.global.add.v4 per tile
__global__ void __launch_bounds__(128, 6) k_layer2(const float* __restrict__ W2,
                                                   int E, int nWarps) {
    __shared__ float shh[4][3][512];    // [warp][buf][16 rows x 32 floats] 24KB
    __shared__ int sOff[NRELS + 1];
    int t = threadIdx.x;
    if (t == 0) {
        int s = 0;
        for (int q = 0; q < NRELS; q++) { sOff[q] = s; s += g_relHist[q]; }
        sOff[NRELS] = s;
    }
    __syncthreads();
    int lane = t & 31;
    int warp = t >> 5;
    int gr   = lane >> 2;      // fragment group row (0..7)
    int tig  = lane & 3;       // thread-in-group
    int grow = lane >> 3;      // gather row-in-quad (0..3)
    int gchk = lane & 7;       // gather 16B chunk within 128B row
    u32 shW = smem_u32(&shh[warp][0][0]);       // buffer stride 2048B, 3 bufs
    const char* sbase = (const char*)&shh[warp][0][0];

    int gw = blockIdx.x * 4 + warp;
    if (gw >= nWarps) return;
    int e    = (int)(((long long)gw * E) / nWarps);
    int eEnd = (int)(((long long)gw + 1) * E / nWarps);

    int r = 0;
    while (e < eEnd) {
        while (sOff[r + 1] <= e) r++;
        int runEnd = min(eEnd, sOff[r + 1]);
        if (e >= runEnd) continue;

        // ---- W2[r] bf16 hi/lo fragments, register-resident (32 regs) ----
        const float* Wr = W2 + r * DIM * DIM;
        u32 bhi[2][4][2], blo[2][4][2];
#pragma unroll
        for (int ks = 0; ks < 2; ks++)
#pragma unroll
            for (int nb = 0; nb < 4; nb++) {
                int k0 = ks * 16 + 2 * tig, n0 = nb * 8 + gr;
                float w00 = __ldg(&Wr[k0 * DIM + n0]);
                float w01 = __ldg(&Wr[(k0 + 1) * DIM + n0]);
                float w10 = __ldg(&Wr[(k0 + 8) * DIM + n0]);
                float w11 = __ldg(&Wr[(k0 + 9) * DIM + n0]);
                u32 h0 = bf16x2(w00, w01);
                u32 h1 = bf16x2(w10, w11);
                bhi[ks][nb][0] = h0;
                bhi[ks][nb][1] = h1;
                blo[ks][nb][0] = bf16x2_lo(w00, w01, h0);
                blo[ks][nb][1] = bf16x2_lo(w10, w11, h1);
            }

        cp_wait0();          // drain previous run before reusing buffers
        __syncwarp();

        // ---- prolog: edata 3 tiles deep; gather tiles e, e+16 into bufs 0,1
        int2 edc = make_int2(0, 0), edn = make_int2(0, 0), ed2 = make_int2(0, 0);
        if (lane < 16 && e + lane < runEnd) edc = __ldg(&g_edata[e + lane]);
        if (lane < 16 && e + 16 + lane < runEnd) edn = __ldg(&g_edata[e + 16 + lane]);
        if (lane < 16 && e + 32 + lane < runEnd) ed2 = __ldg(&g_edata[e + 32 + lane]);
#pragma unroll
        for (int i = 0; i < 4; i++) {
            int row = i * 4 + grow;
            int sk = __shfl_sync(0xffffffffu, edc.x, row);
            cp_async16(shW + row * 128 + ((gchk ^ (row & 7)) * 16),
                       &g_h14[sk * 8 + gchk], (e + row < runEnd) ? 16 : 0);
        }
        cp_commit();
#pragma unroll
        for (int i = 0; i < 4; i++) {
            int row = i * 4 + grow;
            int sk = __shfl_sync(0xffffffffu, edn.x, row);
            cp_async16(shW + 2048 + row * 128 + ((gchk ^ (row & 7)) * 16),
                       &g_h14[sk * 8 + gchk], (e + 16 + row < runEnd) ? 16 : 0);
        }
        cp_commit();

        u32 bOff = 0;                    // compute buffer byte offset (0/2048/4096)
        for (int c = e; c < runEnd; c += 16) {
            // edata three tiles ahead
            int2 ed3 = make_int2(0, 0);
            if (lane < 16 && c + 48 + lane < runEnd) ed3 = __ldg(&g_edata[c + 48 + lane]);

            // gather tile c+32 into buffer (b+2)%3
            {
                u32 gOff = bOff + 4096;
                if (gOff >= 6144) gOff -= 6144;
#pragma unroll
                for (int i = 0; i < 4; i++) {
                    int row = i * 4 + grow;
                    int sk = __shfl_sync(0xffffffffu, ed2.x, row);
                    cp_async16(shW + gOff + row * 128 + ((gchk ^ (row & 7)) * 16),
                               &g_h14[sk * 8 + gchk], (c + 32 + row < runEnd) ? 16 : 0);
                }
            }
            cp_commit();
            cp_wait2();                  // tile c's buffer ready (2 newer pending)
            __syncwarp();

            // ---- compute: 2 ksteps x (A convert + 12 MMAs) ----
            float C00=0,C01=0,C02=0,C03=0, C10=0,C11=0,C12=0,C13=0;
            float C20=0,C21=0,C22=0,C23=0, C30=0,C31=0,C32=0,C33=0;
            const char* sb = sbase + bOff;
#pragma unroll
            for (int ks = 0; ks < 2; ks++) {
                int ch0 = 4 * ks + (tig >> 1);
                int off = (tig & 1) * 8;
                const char* rp0 = sb + gr * 128;
                const char* rp1 = sb + (gr + 8) * 128;
                float2 f0 = *(const float2*)(rp0 + ((ch0 ^ gr) * 16) + off);
                float2 f1 = *(const float2*)(rp1 + ((ch0 ^ gr) * 16) + off);
                float2 f2 = *(const float2*)(rp0 + (((ch0 + 2) ^ gr) * 16) + off);
                float2 f3 = *(const float2*)(rp1 + (((ch0 + 2) ^ gr) * 16) + off);
                u32 ah0 = bf16x2(f0.x, f0.y), ah1 = bf16x2(f1.x, f1.y);
                u32 ah2 = bf16x2(f2.x, f2.y), ah3 = bf16x2(f3.x, f3.y);
                u32 al0 = bf16x2_lo(f0.x, f0.y, ah0);
                u32 al1 = bf16x2_lo(f1.x, f1.y, ah1);
                u32 al2 = bf16x2_lo(f2.x, f2.y, ah2);
                u32 al3 = bf16x2_lo(f3.x, f3.y, ah3);
                mma_bf16(C00,C01,C02,C03, ah0,ah1,ah2,ah3, bhi[ks][0][0], bhi[ks][0][1]);
                mma_bf16(C10,C11,C12,C13, ah0,ah1,ah2,ah3, bhi[ks][1][0], bhi[ks][1][1]);
                mma_bf16(C20,C21,C22,C23, ah0,ah1,ah2,ah3, bhi[ks][2][0], bhi[ks][2][1]);
                mma_bf16(C30,C31,C32,C33, ah0,ah1,ah2,ah3, bhi[ks][3][0], bhi[ks][3][1]);
                mma_bf16(C00,C01,C02,C03, ah0,ah1,ah2,ah3, blo[ks][0][0], blo[ks][0][1]);
                mma_bf16(C10,C11,C12,C13, ah0,ah1,ah2,ah3, blo[ks][1][0], blo[ks][1][1]);
                mma_bf16(C20,C21,C22,C23, ah0,ah1,ah2,ah3, blo[ks][2][0], blo[ks][2][1]);
                mma_bf16(C30,C31,C32,C33, ah0,ah1,ah2,ah3, blo[ks][3][0], blo[ks][3][1]);
                mma_bf16(C00,C01,C02,C03, al0,al1,al2,al3, bhi[ks][0][0], bhi[ks][0][1]);
                mma_bf16(C10,C11,C12,C13, al0,al1,al2,al3, bhi[ks][1][0], bhi[ks][1][1]);
                mma_bf16(C20,C21,C22,C23, al0,al1,al2,al3, bhi[ks][2][0], bhi[ks][2][1]);
                mma_bf16(C30,C31,C32,C33, al0,al1,al2,al3, bhi[ks][3][0], bhi[ks][3][1]);
            }

            // ---- scatter: perm cols, 4 red4/tile ----
            int dA = __shfl_sync(0xffffffffu, edc.y, gr);
            int dB = __shfl_sync(0xffffffffu, edc.y, gr + 8);
            float* pA = (float*)g_h2 + (size_t)dA * DIM + tig * 8;
            float* pB = (float*)g_h2 + (size_t)dB * DIM + tig * 8;
            red4(pA,     C00, C01, C10, C11);
            red4(pA + 4, C20, C21, C30, C31);
            red4(pB,     C02, C03, C12, C13);
            red4(pB + 4, C22, C23, C32, C33);

            edc = edn; edn = ed2; ed2 = ed3;
            bOff += 2048;
            if (bOff == 6144) bOff = 0;
        }
        e = runEnd;
    }
}

// Final: out[v] = relu(h2perm[v] + b2) @ W3 + b3; inverse perm read; resets
// h2 row and (block 0) the rel counters for the next graph replay.
__global__ void k_final(const float* __restrict__ W3, const float* __restrict__ b2,
                        const float* __restrict__ b3, float* __restrict__ out, int N) {
    __shared__ float sW[DIM * DIM];
    __shared__ float sb2[DIM];
    __shared__ float sb3[DIM];
    int t = threadIdx.x;
    for (int i = t; i < DIM * DIM; i += blockDim.x) sW[i] = W3[i];
    if (t < DIM) { sb2[t] = b2[t]; sb3[t] = b3[t]; }
    if (blockIdx.x == 0 && t < NRELS) { g_relHist[t] = 0; g_relCur[t] = 0; }
    __syncthreads();
    int lane = t & 31;
    int wpb = blockDim.x >> 5;
    int pos = ((lane & 7) >> 1) * 8 + (lane >> 3) * 2 + (lane & 1);
    float* h2 = (float*)g_h2;
    for (int v = blockIdx.x * wpb + (t >> 5); v < N; v += gridDim.x * wpb) {
        float h = fmaxf(h2[v * DIM + pos] + sb2[lane], 0.0f);
        h2[v * DIM + lane] = 0.0f;
        float acc = sb3[lane];
#pragma unroll
        for (int i = 0; i < DIM; i++) {
            float hi = __shfl_sync(0xffffffffu, h, i);
            acc += hi * sW[i * DIM + lane];
        }
        out[v * DIM + lane] = acc;
    }
}

// ---------------- launch ----------------
extern "C" void kernel_launch(void* const* d_in, const int* in_sizes, int n_in,
                              void* d_out, int out_size) {
    const int* src = (const int*)d_in[0];
    const int* dst = (const int*)d_in[1];
    const int* et  = (const int*)d_in[2];
    int base = (n_in > 3 && in_sizes[3] == 1) ? 4 : 3;
    const float* W1 = (const float*)d_in[base + 0];
    const float* b1 = (const float*)d_in[base + 1];
    const float* W2 = (const float*)d_in[base + 2];
    const float* b2 = (const float*)d_in[base + 3];
    const float* W3 = (const float*)d_in[base + 4];
    const float* b3 = (const float*)d_in[base + 5];

    int E = in_sizes[0];
    int N = out_size / DIM;
    float* out = (float*)d_out;

    int edgeBlocks4 = (E / 4 + 255) / 256 + 1;
    k_hist<<<edgeBlocks4, 256>>>(dst, et, E);          // launch 0
    k_scatter<<<edgeBlocks4, 256>>>(src, dst, et, E);  // launch 1

    int nodeBlocks = (N + 7) / 8;
    k_layer1<<<nodeBlocks, 256>>>(W1, b1, N);          // launch 2

    const int nWarps = 3552;   // 148 SMs x 6 blocks x 4 warps, one wave
    k_layer2<<<nWarps / 4, 128>>>(W2, E, nWarps);      // launch 3 (profiled slot)

    k_final<<<nodeBlocks, 256>>>(W3, b2, b3, out, N);  // launch 4
}

// round 14
// speedup vs baseline: 2.5765x; 2.5765x over previous
#include <cuda_runtime.h>

#define NRELS 19
#define CPAD  20
#define DIM   32
#define MAXN  100000
#define MAXE  1600000

typedef unsigned int u32;

// ---------------- static scratch (zero-init; each consumer kernel resets
// what it read, so every graph replay starts pristine) ----------------------
static __device__ int4   g_cnt4[MAXN * (CPAD / 4)];   // (node,rel) counts
static __device__ float4 g_h14[MAXN * (DIM / 4)];     // layer-1 activations
static __device__ float4 g_h2[MAXN * (DIM / 4)];      // layer-2 accumulator (perm cols)
static __device__ int2   g_edata[MAXE];               // relation-bucketed (src,dst)
static __device__ int    g_relHist[NRELS];
static __device__ int    g_relCur[NRELS];

// ---------------- helpers ----------------
__device__ __forceinline__ void red4(float* p, float a, float b, float c, float d) {
    asm volatile("red.global.add.v4.f32 [%0], {%1, %2, %3, %4};"
                 :: "l"(p), "f"(a), "f"(b), "f"(c), "f"(d) : "memory");
}
__device__ __forceinline__ u32 smem_u32(const void* p) {
    return (u32)__cvta_generic_to_shared(p);
}
__device__ __forceinline__ void cp_async16(u32 dst, const void* src, int srcsize) {
    asm volatile("cp.async.cg.shared.global [%0], [%1], 16, %2;"
                 :: "r"(dst), "l"(src), "r"(srcsize));
}
__device__ __forceinline__ void cp_commit() { asm volatile("cp.async.commit_group;"); }
__device__ __forceinline__ void cp_wait2()  { asm volatile("cp.async.wait_group 2;"); }
__device__ __forceinline__ void cp_wait0()  { asm volatile("cp.async.wait_group 0;"); }
// pack {lo, hi} floats into bf16x2 (element0 = lo)
__device__ __forceinline__ u32 bf16x2(float lo, float hi) {
    u32 r; asm("cvt.rn.bf16x2.f32 %0, %1, %2;" : "=r"(r) : "f"(hi), "f"(lo)); return r;
}
// residual of a float2 after removing its bf16x2 hi part
__device__ __forceinline__ u32 bf16x2_lo(float x, float y, u32 hi) {
    float lx = x - __uint_as_float(hi << 16);
    float ly = y - __uint_as_float(hi & 0xFFFF0000u);
    return bf16x2(lx, ly);
}
// m16n8k16 bf16 MMA, fp32 accumulate in place.
__device__ __forceinline__ void mma_bf16(float& c0, float& c1, float& c2, float& c3,
                                         u32 a0, u32 a1, u32 a2, u32 a3,
                                         u32 b0, u32 b1) {
    asm volatile("mma.sync.aligned.m16n8k16.row.col.f32.bf16.bf16.f32 "
                 "{%0,%1,%2,%3}, {%4,%5,%6,%7}, {%8,%9}, {%0,%1,%2,%3};"
                 : "+f"(c0), "+f"(c1), "+f"(c2), "+f"(c3)
                 : "r"(a0), "r"(a1), "r"(a2), "r"(a3), "r"(b0), "r"(b1));
}

// ---------------- kernels (order: hist, scatter, layer1, LAYER2, final) ----

__global__ void k_hist(const int* __restrict__ dst, const int* __restrict__ et, int E) {
    __shared__ int sh[NRELS];
    if (threadIdx.x < NRELS) sh[threadIdx.x] = 0;
    __syncthreads();
    int* cnt = (int*)g_cnt4;
    int e0 = (blockIdx.x * blockDim.x + threadIdx.x) * 4;
    if (e0 + 3 < E) {
        int4 d4 = *(const int4*)&dst[e0];
        int4 r4 = *(const int4*)&et[e0];
        atomicAdd(&cnt[d4.x * CPAD + r4.x], 1);
        atomicAdd(&cnt[d4.y * CPAD + r4.y], 1);
        atomicAdd(&cnt[d4.z * CPAD + r4.z], 1);
        atomicAdd(&cnt[d4.w * CPAD + r4.w], 1);
        atomicAdd(&sh[r4.x], 1); atomicAdd(&sh[r4.y], 1);
        atomicAdd(&sh[r4.z], 1); atomicAdd(&sh[r4.w], 1);
    } else {
        for (int e = e0; e < E; e++) {
            int r = et[e];
            atomicAdd(&cnt[dst[e] * CPAD + r], 1);
            atomicAdd(&sh[r], 1);
        }
    }
    __syncthreads();
    if (threadIdx.x < NRELS) atomicAdd(&g_relHist[threadIdx.x], sh[threadIdx.x]);
}

__global__ void k_scatter(const int* __restrict__ src, const int* __restrict__ dst,
                          const int* __restrict__ et, int E) {
    __shared__ int sOff[NRELS];
    __shared__ int shCnt[NRELS];
    __shared__ int shBase[NRELS];
    int t = threadIdx.x;
    if (t < NRELS) {
        shCnt[t] = 0;
        int s = 0;
#pragma unroll
        for (int q = 0; q < NRELS; q++) {
            if (q == t) sOff[t] = s;
            s += g_relHist[q];
        }
    }
    __syncthreads();
    int e0 = (blockIdx.x * blockDim.x + t) * 4;
    int r[4], s[4], d[4], lp[4];
    int cnt = 0;
    if (e0 + 3 < E) {
        int4 s4 = *(const int4*)&src[e0];
        int4 d4 = *(const int4*)&dst[e0];
        int4 r4 = *(const int4*)&et[e0];
        s[0]=s4.x; s[1]=s4.y; s[2]=s4.z; s[3]=s4.w;
        d[0]=d4.x; d[1]=d4.y; d[2]=d4.z; d[3]=d4.w;
        r[0]=r4.x; r[1]=r4.y; r[2]=r4.z; r[3]=r4.w;
        cnt = 4;
    } else {
        for (int e = e0; e < E; e++) {
            s[cnt]=src[e]; d[cnt]=dst[e]; r[cnt]=et[e]; cnt++;
        }
    }
    for (int k = 0; k < cnt; k++) lp[k] = atomicAdd(&shCnt[r[k]], 1);
    __syncthreads();
    if (t < NRELS) shBase[t] = sOff[t] + atomicAdd(&g_relCur[t], shCnt[t]);
    __syncthreads();
    for (int k = 0; k < cnt; k++)
        g_edata[shBase[r[k]] + lp[k]] = make_int2(s[k], d[k]);
}

// Layer 1; also RESETS cnt rows to zero after reading.
__global__ void k_layer1(const float* __restrict__ W1, const float* __restrict__ b1, int N) {
    __shared__ float sW[NRELS * DIM];
    __shared__ float sb[DIM];
    int t = threadIdx.x;
    for (int i = t; i < NRELS * DIM; i += blockDim.x) sW[i] = W1[i];
    if (t < DIM) sb[t] = b1[t];
    __syncthreads();
    int lane = t & 31;
    int wpb = blockDim.x >> 5;
    float* h1 = (float*)g_h14;
    for (int v = blockIdx.x * wpb + (t >> 5); v < N; v += gridDim.x * wpb) {
        int4* crow = &g_cnt4[v * (CPAD / 4)];
        int c[CPAD];
#pragma unroll
        for (int q = 0; q < CPAD / 4; q++) {
            int4 cc = __ldg(&crow[q]);
            c[q * 4 + 0] = cc.x; c[q * 4 + 1] = cc.y;
            c[q * 4 + 2] = cc.z; c[q * 4 + 3] = cc.w;
        }
        float acc = sb[lane];
#pragma unroll
        for (int r = 0; r < NRELS; r++)
            acc += (float)c[r] * sW[r * DIM + lane];
        h1[v * DIM + lane] = fmaxf(acc, 0.0f);
        if (lane < CPAD / 4) crow[lane] = make_int4(0, 0, 0, 0);
    }
}

// Layer 2 (hot): bf16 tensor tiles, 16 edges per tile per warp (round-12 core):
//   D[16 x 32] += A[16 x 32] (gathered h1 rows) @ W2[rel] (32 x 32)
// mma.m16n8k16.bf16, 2x2 hi/lo split, 3 terms.  Round-14 diff vs the 191 µs
// winner is ONLY pipeline depth: 3 smem buffers + wait_group 2 (gather for
// tile c+32 in flight during compute of tile c).  Occupancy stays at the
// NATURAL 5 blocks/SM (reg budget 102 >= the ~98 this needs -> no spill).
__global__ void __launch_bounds__(128, 5) k_layer2(const float* __restrict__ W2,
                                                   int E, int nWarps) {
    __shared__ float shh[4][3][512];    // [warp][buf][16 rows x 32 floats] 24KB
    __shared__ int sOff[NRELS + 1];
    int t = threadIdx.x;
    if (t == 0) {
        int s = 0;
        for (int q = 0; q < NRELS; q++) { sOff[q] = s; s += g_relHist[q]; }
        sOff[NRELS] = s;
    }
    __syncthreads();
    int lane = t & 31;
    int warp = t >> 5;
    int gr   = lane >> 2;      // fragment group row (0..7)
    int tig  = lane & 3;       // thread-in-group
    int grow = lane >> 3;      // gather row-in-quad (0..3)
    int gchk = lane & 7;       // gather 16B chunk within 128B row
    u32 shW = smem_u32(&shh[warp][0][0]);       // buffer stride 2048B, 3 bufs
    const char* sbase = (const char*)&shh[warp][0][0];

    int gw = blockIdx.x * 4 + warp;
    if (gw >= nWarps) return;
    int e    = (int)(((long long)gw * E) / nWarps);
    int eEnd = (int)(((long long)(gw + 1) * E) / nWarps);

    int r = 0;
    while (e < eEnd) {
        while (sOff[r + 1] <= e) r++;
        int runEnd = min(eEnd, sOff[r + 1]);
        if (e >= runEnd) continue;

        // ---- W2[r] bf16 hi/lo fragments, register-resident (32 regs) ----
        const float* Wr = W2 + r * DIM * DIM;
        u32 bhi[2][4][2], blo[2][4][2];
#pragma unroll
        for (int ks = 0; ks < 2; ks++)
#pragma unroll
            for (int nb = 0; nb < 4; nb++) {
                int k0 = ks * 16 + 2 * tig, n0 = nb * 8 + gr;
                float w00 = __ldg(&Wr[k0 * DIM + n0]);
                float w01 = __ldg(&Wr[(k0 + 1) * DIM + n0]);
                float w10 = __ldg(&Wr[(k0 + 8) * DIM + n0]);
                float w11 = __ldg(&Wr[(k0 + 9) * DIM + n0]);
                u32 h0 = bf16x2(w00, w01);
                u32 h1 = bf16x2(w10, w11);
                bhi[ks][nb][0] = h0;
                bhi[ks][nb][1] = h1;
                blo[ks][nb][0] = bf16x2_lo(w00, w01, h0);
                blo[ks][nb][1] = bf16x2_lo(w10, w11, h1);
            }

        cp_wait0();          // drain previous run before reusing buffers
        __syncwarp();

        // ---- prolog: edata 3 tiles deep; gather tiles e, e+16 into bufs 0,1
        int2 edc = make_int2(0, 0), edn = make_int2(0, 0), ed2 = make_int2(0, 0);
        if (lane < 16 && e + lane < runEnd) edc = __ldg(&g_edata[e + lane]);
        if (lane < 16 && e + 16 + lane < runEnd) edn = __ldg(&g_edata[e + 16 + lane]);
        if (lane < 16 && e + 32 + lane < runEnd) ed2 = __ldg(&g_edata[e + 32 + lane]);
#pragma unroll
        for (int i = 0; i < 4; i++) {
            int row = i * 4 + grow;
            int sk = __shfl_sync(0xffffffffu, edc.x, row);
            cp_async16(shW + row * 128 + ((gchk ^ (row & 7)) * 16),
                       &g_h14[sk * 8 + gchk], (e + row < runEnd) ? 16 : 0);
        }
        cp_commit();
#pragma unroll
        for (int i = 0; i < 4; i++) {
            int row = i * 4 + grow;
            int sk = __shfl_sync(0xffffffffu, edn.x, row);
            cp_async16(shW + 2048 + row * 128 + ((gchk ^ (row & 7)) * 16),
                       &g_h14[sk * 8 + gchk], (e + 16 + row < runEnd) ? 16 : 0);
        }
        cp_commit();

        u32 bOff = 0;                    // compute buffer byte offset (0/2048/4096)
        for (int c = e; c < runEnd; c += 16) {
            // edata three tiles ahead
            int2 ed3 = make_int2(0, 0);
            if (lane < 16 && c + 48 + lane < runEnd) ed3 = __ldg(&g_edata[c + 48 + lane]);

            // gather tile c+32 into buffer (b+2)%3
            {
                u32 gOff = bOff + 4096;
                if (gOff >= 6144) gOff -= 6144;
#pragma unroll
                for (int i = 0; i < 4; i++) {
                    int row = i * 4 + grow;
                    int sk = __shfl_sync(0xffffffffu, ed2.x, row);
                    cp_async16(shW + gOff + row * 128 + ((gchk ^ (row & 7)) * 16),
                               &g_h14[sk * 8 + gchk], (c + 32 + row < runEnd) ? 16 : 0);
                }
            }
            cp_commit();
            cp_wait2();                  // tile c's buffer ready (2 newer pending)
            __syncwarp();

            // ---- compute: 2 ksteps x (A convert + 12 MMAs) ----
            float C00=0,C01=0,C02=0,C03=0, C10=0,C11=0,C12=0,C13=0;
            float C20=0,C21=0,C22=0,C23=0, C30=0,C31=0,C32=0,C33=0;
            const char* sb = sbase + bOff;
#pragma unroll
            for (int ks = 0; ks < 2; ks++) {
                int ch0 = 4 * ks + (tig >> 1);
                int off = (tig & 1) * 8;
                const char* rp0 = sb + gr * 128;
                const char* rp1 = sb + (gr + 8) * 128;
                float2 f0 = *(const float2*)(rp0 + ((ch0 ^ gr) * 16) + off);
                float2 f1 = *(const float2*)(rp1 + ((ch0 ^ gr) * 16) + off);
                float2 f2 = *(const float2*)(rp0 + (((ch0 + 2) ^ gr) * 16) + off);
                float2 f3 = *(const float2*)(rp1 + (((ch0 + 2) ^ gr) * 16) + off);
                u32 ah0 = bf16x2(f0.x, f0.y), ah1 = bf16x2(f1.x, f1.y);
                u32 ah2 = bf16x2(f2.x, f2.y), ah3 = bf16x2(f3.x, f3.y);
                u32 al0 = bf16x2_lo(f0.x, f0.y, ah0);
                u32 al1 = bf16x2_lo(f1.x, f1.y, ah1);
                u32 al2 = bf16x2_lo(f2.x, f2.y, ah2);
                u32 al3 = bf16x2_lo(f3.x, f3.y, ah3);
                mma_bf16(C00,C01,C02,C03, ah0,ah1,ah2,ah3, bhi[ks][0][0], bhi[ks][0][1]);
                mma_bf16(C10,C11,C12,C13, ah0,ah1,ah2,ah3, bhi[ks][1][0], bhi[ks][1][1]);
                mma_bf16(C20,C21,C22,C23, ah0,ah1,ah2,ah3, bhi[ks][2][0], bhi[ks][2][1]);
                mma_bf16(C30,C31,C32,C33, ah0,ah1,ah2,ah3, bhi[ks][3][0], bhi[ks][3][1]);
                mma_bf16(C00,C01,C02,C03, ah0,ah1,ah2,ah3, blo[ks][0][0], blo[ks][0][1]);
                mma_bf16(C10,C11,C12,C13, ah0,ah1,ah2,ah3, blo[ks][1][0], blo[ks][1][1]);
                mma_bf16(C20,C21,C22,C23, ah0,ah1,ah2,ah3, blo[ks][2][0], blo[ks][2][1]);
                mma_bf16(C30,C31,C32,C33, ah0,ah1,ah2,ah3, blo[ks][3][0], blo[ks][3][1]);
                mma_bf16(C00,C01,C02,C03, al0,al1,al2,al3, bhi[ks][0][0], bhi[ks][0][1]);
                mma_bf16(C10,C11,C12,C13, al0,al1,al2,al3, bhi[ks][1][0], bhi[ks][1][1]);
                mma_bf16(C20,C21,C22,C23, al0,al1,al2,al3, bhi[ks][2][0], bhi[ks][2][1]);
                mma_bf16(C30,C31,C32,C33, al0,al1,al2,al3, bhi[ks][3][0], bhi[ks][3][1]);
            }

            // ---- scatter: perm cols, 4 red4/tile ----
            int dA = __shfl_sync(0xffffffffu, edc.y, gr);
            int dB = __shfl_sync(0xffffffffu, edc.y, gr + 8);
            float* pA = (float*)g_h2 + (size_t)dA * DIM + tig * 8;
            float* pB = (float*)g_h2 + (size_t)dB * DIM + tig * 8;
            red4(pA,     C00, C01, C10, C11);
            red4(pA + 4, C20, C21, C30, C31);
            red4(pB,     C02, C03, C12, C13);
            red4(pB + 4, C22, C23, C32, C33);

            edc = edn; edn = ed2; ed2 = ed3;
            bOff += 2048;
            if (bOff == 6144) bOff = 0;
        }
        e = runEnd;
    }
}

// Final: out[v] = relu(h2perm[v] + b2) @ W3 + b3; inverse perm read; resets
// h2 row and (block 0) the rel counters for the next graph replay.
__global__ void k_final(const float* __restrict__ W3, const float* __restrict__ b2,
                        const float* __restrict__ b3, float* __restrict__ out, int N) {
    __shared__ float sW[DIM * DIM];
    __shared__ float sb2[DIM];
    __shared__ float sb3[DIM];
    int t = threadIdx.x;
    for (int i = t; i < DIM * DIM; i += blockDim.x) sW[i] = W3[i];
    if (t < DIM) { sb2[t] = b2[t]; sb3[t] = b3[t]; }
    if (blockIdx.x == 0 && t < NRELS) { g_relHist[t] = 0; g_relCur[t] = 0; }
    __syncthreads();
    int lane = t & 31;
    int wpb = blockDim.x >> 5;
    int pos = ((lane & 7) >> 1) * 8 + (lane >> 3) * 2 + (lane & 1);
    float* h2 = (float*)g_h2;
    for (int v = blockIdx.x * wpb + (t >> 5); v < N; v += gridDim.x * wpb) {
        float h = fmaxf(h2[v * DIM + pos] + sb2[lane], 0.0f);
        h2[v * DIM + lane] = 0.0f;
        float acc = sb3[lane];
#pragma unroll
        for (int i = 0; i < DIM; i++) {
            float hi = __shfl_sync(0xffffffffu, h, i);
            acc += hi * sW[i * DIM + lane];
        }
        out[v * DIM + lane] = acc;
    }
}

// ---------------- launch ----------------
extern "C" void kernel_launch(void* const* d_in, const int* in_sizes, int n_in,
                              void* d_out, int out_size) {
    const int* src = (const int*)d_in[0];
    const int* dst = (const int*)d_in[1];
    const int* et  = (const int*)d_in[2];
    int base = (n_in > 3 && in_sizes[3] == 1) ? 4 : 3;
    const float* W1 = (const float*)d_in[base + 0];
    const float* b1 = (const float*)d_in[base + 1];
    const float* W2 = (const float*)d_in[base + 2];
    const float* b2 = (const float*)d_in[base + 3];
    const float* W3 = (const float*)d_in[base + 4];
    const float* b3 = (const float*)d_in[base + 5];

    int E = in_sizes[0];
    int N = out_size / DIM;
    float* out = (float*)d_out;

    int edgeBlocks4 = (E / 4 + 255) / 256 + 1;
    k_hist<<<edgeBlocks4, 256>>>(dst, et, E);          // launch 0
    k_scatter<<<edgeBlocks4, 256>>>(src, dst, et, E);  // launch 1

    int nodeBlocks = (N + 7) / 8;
    k_layer1<<<nodeBlocks, 256>>>(W1, b1, N);          // launch 2

    const int nWarps = 2960;   // 148 SMs x 5 blocks x 4 warps, one wave
    k_layer2<<<nWarps / 4, 128>>>(W2, E, nWarps);      // launch 3 (profiled slot)

    k_final<<<nodeBlocks, 256>>>(W3, b2, b3, out, N);  // launch 4
}

// round 15
// speedup vs baseline: 2.5808x; 1.0017x over previous
#include <cuda_runtime.h>

#define NRELS 19
#define CPAD  20
#define DIM   32
#define MAXN  100000
#define MAXE  1600000

typedef unsigned int u32;

// ---------------- static scratch (zero-init; each consumer kernel resets
// what it read, so every graph replay starts pristine) ----------------------
static __device__ int4   g_cnt4[MAXN * (CPAD / 4)];   // (node,rel) counts
static __device__ u32    g_h1u[MAXN * DIM];           // h1, SPLIT bf16, fragment order:
                                                      // row=128B: [hi 16 u32][lo 16 u32],
                                                      // slot s <-> pair p=(s>>3)*8+((s&7)>>1)+(s&1)*4
static __device__ float4 g_h2[MAXN * (DIM / 4)];      // layer-2 accumulator (perm cols)
static __device__ int2   g_edata[MAXE];               // relation-bucketed (src,dst)
static __device__ int    g_relHist[NRELS];
static __device__ int    g_relCur[NRELS];

// ---------------- helpers ----------------
__device__ __forceinline__ void red4(float* p, float a, float b, float c, float d) {
    asm volatile("red.global.add.v4.f32 [%0], {%1, %2, %3, %4};"
                 :: "l"(p), "f"(a), "f"(b), "f"(c), "f"(d) : "memory");
}
__device__ __forceinline__ u32 smem_u32(const void* p) {
    return (u32)__cvta_generic_to_shared(p);
}
__device__ __forceinline__ void cp_async16(u32 dst, const void* src, int srcsize) {
    asm volatile("cp.async.cg.shared.global [%0], [%1], 16, %2;"
                 :: "r"(dst), "l"(src), "r"(srcsize));
}
__device__ __forceinline__ void cp_commit() { asm volatile("cp.async.commit_group;"); }
__device__ __forceinline__ void cp_wait2()  { asm volatile("cp.async.wait_group 2;"); }
__device__ __forceinline__ void cp_wait0()  { asm volatile("cp.async.wait_group 0;"); }
// pack {lo, hi} floats into bf16x2 (element0 = lo)
__device__ __forceinline__ u32 bf16x2(float lo, float hi) {
    u32 r; asm("cvt.rn.bf16x2.f32 %0, %1, %2;" : "=r"(r) : "f"(hi), "f"(lo)); return r;
}
// residual of a float2 after removing its bf16x2 hi part
__device__ __forceinline__ u32 bf16x2_lo(float x, float y, u32 hi) {
    float lx = x - __uint_as_float(hi << 16);
    float ly = y - __uint_as_float(hi & 0xFFFF0000u);
    return bf16x2(lx, ly);
}
// m16n8k16 bf16 MMA, fp32 accumulate in place.
__device__ __forceinline__ void mma_bf16(float& c0, float& c1, float& c2, float& c3,
                                         u32 a0, u32 a1, u32 a2, u32 a3,
                                         u32 b0, u32 b1) {
    asm volatile("mma.sync.aligned.m16n8k16.row.col.f32.bf16.bf16.f32 "
                 "{%0,%1,%2,%3}, {%4,%5,%6,%7}, {%8,%9}, {%0,%1,%2,%3};"
                 : "+f"(c0), "+f"(c1), "+f"(c2), "+f"(c3)
                 : "r"(a0), "r"(a1), "r"(a2), "r"(a3), "r"(b0), "r"(b1));
}

// ---------------- kernels (order: hist, scatter, layer1, LAYER2, final) ----

__global__ void k_hist(const int* __restrict__ dst, const int* __restrict__ et, int E) {
    __shared__ int sh[NRELS];
    if (threadIdx.x < NRELS) sh[threadIdx.x] = 0;
    __syncthreads();
    int* cnt = (int*)g_cnt4;
    int e0 = (blockIdx.x * blockDim.x + threadIdx.x) * 4;
    if (e0 + 3 < E) {
        int4 d4 = *(const int4*)&dst[e0];
        int4 r4 = *(const int4*)&et[e0];
        atomicAdd(&cnt[d4.x * CPAD + r4.x], 1);
        atomicAdd(&cnt[d4.y * CPAD + r4.y], 1);
        atomicAdd(&cnt[d4.z * CPAD + r4.z], 1);
        atomicAdd(&cnt[d4.w * CPAD + r4.w], 1);
        atomicAdd(&sh[r4.x], 1); atomicAdd(&sh[r4.y], 1);
        atomicAdd(&sh[r4.z], 1); atomicAdd(&sh[r4.w], 1);
    } else {
        for (int e = e0; e < E; e++) {
            int r = et[e];
            atomicAdd(&cnt[dst[e] * CPAD + r], 1);
            atomicAdd(&sh[r], 1);
        }
    }
    __syncthreads();
    if (threadIdx.x < NRELS) atomicAdd(&g_relHist[threadIdx.x], sh[threadIdx.x]);
}

__global__ void k_scatter(const int* __restrict__ src, const int* __restrict__ dst,
                          const int* __restrict__ et, int E) {
    __shared__ int sOff[NRELS];
    __shared__ int shCnt[NRELS];
    __shared__ int shBase[NRELS];
    int t = threadIdx.x;
    if (t < NRELS) {
        shCnt[t] = 0;
        int s = 0;
#pragma unroll
        for (int q = 0; q < NRELS; q++) {
            if (q == t) sOff[t] = s;
            s += g_relHist[q];
        }
    }
    __syncthreads();
    int e0 = (blockIdx.x * blockDim.x + t) * 4;
    int r[4], s[4], d[4], lp[4];
    int cnt = 0;
    if (e0 + 3 < E) {
        int4 s4 = *(const int4*)&src[e0];
        int4 d4 = *(const int4*)&dst[e0];
        int4 r4 = *(const int4*)&et[e0];
        s[0]=s4.x; s[1]=s4.y; s[2]=s4.z; s[3]=s4.w;
        d[0]=d4.x; d[1]=d4.y; d[2]=d4.z; d[3]=d4.w;
        r[0]=r4.x; r[1]=r4.y; r[2]=r4.z; r[3]=r4.w;
        cnt = 4;
    } else {
        for (int e = e0; e < E; e++) {
            s[cnt]=src[e]; d[cnt]=dst[e]; r[cnt]=et[e]; cnt++;
        }
    }
    for (int k = 0; k < cnt; k++) lp[k] = atomicAdd(&shCnt[r[k]], 1);
    __syncthreads();
    if (t < NRELS) shBase[t] = sOff[t] + atomicAdd(&g_relCur[t], shCnt[t]);
    __syncthreads();
    for (int k = 0; k < cnt; k++)
        g_edata[shBase[r[k]] + lp[k]] = make_int2(s[k], d[k]);
}

// Layer 1: h1 = relu(cnt @ W1 + b1), written as SPLIT bf16 in fragment order
// (hot-loop conversions move here, once per node instead of once per edge).
// Also RESETS cnt rows after reading.
__global__ void k_layer1(const float* __restrict__ W1, const float* __restrict__ b1, int N) {
    __shared__ float sW[NRELS * DIM];
    __shared__ float sb[DIM];
    int t = threadIdx.x;
    for (int i = t; i < NRELS * DIM; i += blockDim.x) sW[i] = W1[i];
    if (t < DIM) sb[t] = b1[t];
    __syncthreads();
    int lane = t & 31;
    int wpb = blockDim.x >> 5;
    // slot this lane writes: lanes 0-15 write hi[slot], 16-31 write lo[slot]
    int slot = lane & 15;
    int pr = ((slot >> 3) << 3) + ((slot & 7) >> 1) + ((slot & 1) << 2);  // pair index
    for (int v = blockIdx.x * wpb + (t >> 5); v < N; v += gridDim.x * wpb) {
        int4* crow = &g_cnt4[v * (CPAD / 4)];
        int c[CPAD];
#pragma unroll
        for (int q = 0; q < CPAD / 4; q++) {
            int4 cc = __ldg(&crow[q]);
            c[q * 4 + 0] = cc.x; c[q * 4 + 1] = cc.y;
            c[q * 4 + 2] = cc.z; c[q * 4 + 3] = cc.w;
        }
        float acc = sb[lane];
#pragma unroll
        for (int r = 0; r < NRELS; r++)
            acc += (float)c[r] * sW[r * DIM + lane];
        float h = fmaxf(acc, 0.0f);
        // gather this lane's pair values and emit hi (lanes<16) / lo (lanes>=16)
        float hx = __shfl_sync(0xffffffffu, h, 2 * pr);
        float hy = __shfl_sync(0xffffffffu, h, 2 * pr + 1);
        u32 hi = bf16x2(hx, hy);
        u32 val = (lane < 16) ? hi : bf16x2_lo(hx, hy, hi);
        g_h1u[v * DIM + (lane < 16 ? slot : 16 + slot)] = val;
        if (lane < CPAD / 4) crow[lane] = make_int4(0, 0, 0, 0);
    }
}

// Layer 2 (hot): bf16 tensor tiles, 16 edges/tile/warp, h1 PRE-SPLIT:
//   D[16 x 32] += A[16 x 32] @ W2[rel], mma.m16n8k16.bf16, 3 split terms.
// Hot loop now has ZERO conversion math: A hi/lo fragments come straight from
// smem as 8 LDS.64 per tile (fragment-ordered rows).  3-stage cp.async
// pipeline, natural 5 blocks/SM, perm-column red4 scatter.
__global__ void __launch_bounds__(128, 5) k_layer2(const float* __restrict__ W2,
                                                   int E, int nWarps) {
    __shared__ u32 shh[4][3][512];      // [warp][buf][16 rows x 32 u32] 24KB
    __shared__ int sOff[NRELS + 1];
    int t = threadIdx.x;
    if (t == 0) {
        int s = 0;
        for (int q = 0; q < NRELS; q++) { sOff[q] = s; s += g_relHist[q]; }
        sOff[NRELS] = s;
    }
    __syncthreads();
    int lane = t & 31;
    int warp = t >> 5;
    int gr   = lane >> 2;      // fragment group row (0..7)
    int tig  = lane & 3;       // thread-in-group
    int grow = lane >> 3;      // gather row-in-quad (0..3)
    int gchk = lane & 7;       // gather 16B chunk within 128B row
    u32 shW = smem_u32(&shh[warp][0][0]);       // buffer stride 2048B, 3 bufs
    const char* sbase = (const char*)&shh[warp][0][0];

    int gw = blockIdx.x * 4 + warp;
    if (gw >= nWarps) return;
    int e    = (int)(((long long)gw * E) / nWarps);
    int eEnd = (int)(((long long)(gw + 1) * E) / nWarps);

    int r = 0;
    while (e < eEnd) {
        while (sOff[r + 1] <= e) r++;
        int runEnd = min(eEnd, sOff[r + 1]);
        if (e >= runEnd) continue;

        // ---- W2[r] bf16 hi/lo fragments, register-resident (32 regs) ----
        const float* Wr = W2 + r * DIM * DIM;
        u32 bhi[2][4][2], blo[2][4][2];
#pragma unroll
        for (int ks = 0; ks < 2; ks++)
#pragma unroll
            for (int nb = 0; nb < 4; nb++) {
                int k0 = ks * 16 + 2 * tig, n0 = nb * 8 + gr;
                float w00 = __ldg(&Wr[k0 * DIM + n0]);
                float w01 = __ldg(&Wr[(k0 + 1) * DIM + n0]);
                float w10 = __ldg(&Wr[(k0 + 8) * DIM + n0]);
                float w11 = __ldg(&Wr[(k0 + 9) * DIM + n0]);
                u32 h0 = bf16x2(w00, w01);
                u32 h1 = bf16x2(w10, w11);
                bhi[ks][nb][0] = h0;
                bhi[ks][nb][1] = h1;
                blo[ks][nb][0] = bf16x2_lo(w00, w01, h0);
                blo[ks][nb][1] = bf16x2_lo(w10, w11, h1);
            }

        cp_wait0();          // drain previous run before reusing buffers
        __syncwarp();

        // ---- prolog: edata 3 tiles deep; gather tiles e, e+16 into bufs 0,1
        int2 edc = make_int2(0, 0), edn = make_int2(0, 0), ed2 = make_int2(0, 0);
        if (lane < 16 && e + lane < runEnd) edc = __ldg(&g_edata[e + lane]);
        if (lane < 16 && e + 16 + lane < runEnd) edn = __ldg(&g_edata[e + 16 + lane]);
        if (lane < 16 && e + 32 + lane < runEnd) ed2 = __ldg(&g_edata[e + 32 + lane]);
#pragma unroll
        for (int i = 0; i < 4; i++) {
            int row = i * 4 + grow;
            int sk = __shfl_sync(0xffffffffu, edc.x, row);
            cp_async16(shW + row * 128 + ((gchk ^ (row & 7)) * 16),
                       &g_h1u[sk * DIM + gchk * 4], (e + row < runEnd) ? 16 : 0);
        }
        cp_commit();
#pragma unroll
        for (int i = 0; i < 4; i++) {
            int row = i * 4 + grow;
            int sk = __shfl_sync(0xffffffffu, edn.x, row);
            cp_async16(shW + 2048 + row * 128 + ((gchk ^ (row & 7)) * 16),
                       &g_h1u[sk * DIM + gchk * 4], (e + 16 + row < runEnd) ? 16 : 0);
        }
        cp_commit();

        u32 bOff = 0;                    // compute buffer byte offset (0/2048/4096)
        for (int c = e; c < runEnd; c += 16) {
            // edata three tiles ahead
            int2 ed3 = make_int2(0, 0);
            if (lane < 16 && c + 48 + lane < runEnd) ed3 = __ldg(&g_edata[c + 48 + lane]);

            // gather tile c+32 into buffer (b+2)%3
            {
                u32 gOff = bOff + 4096;
                if (gOff >= 6144) gOff -= 6144;
#pragma unroll
                for (int i = 0; i < 4; i++) {
                    int row = i * 4 + grow;
                    int sk = __shfl_sync(0xffffffffu, ed2.x, row);
                    cp_async16(shW + gOff + row * 128 + ((gchk ^ (row & 7)) * 16),
                               &g_h1u[sk * DIM + gchk * 4], (c + 32 + row < runEnd) ? 16 : 0);
                }
            }
            cp_commit();
            cp_wait2();                  // tile c's buffer ready (2 newer pending)
            __syncwarp();

            // ---- compute: 2 ksteps x (4 LDS.64 + 12 MMAs), no conversions ----
            float C00=0,C01=0,C02=0,C03=0, C10=0,C11=0,C12=0,C13=0;
            float C20=0,C21=0,C22=0,C23=0, C30=0,C31=0,C32=0,C33=0;
            const char* sb = sbase + bOff;
            const char* rp0 = sb + gr * 128;
            const char* rp1 = sb + (gr + 8) * 128;
            int rem = (tig & 1) * 8;
#pragma unroll
            for (int ks = 0; ks < 2; ks++) {
                int ch = ks * 2 + (tig >> 1);            // hi chunk; lo = ch+4
                uint2 ahp0 = *(const uint2*)(rp0 + (((ch)     ^ gr) * 16) + rem);  // ah0, ah2
                uint2 ahp1 = *(const uint2*)(rp1 + (((ch)     ^ gr) * 16) + rem);  // ah1, ah3
                uint2 alp0 = *(const uint2*)(rp0 + (((ch + 4) ^ gr) * 16) + rem);  // al0, al2
                uint2 alp1 = *(const uint2*)(rp1 + (((ch + 4) ^ gr) * 16) + rem);  // al1, al3
                mma_bf16(C00,C01,C02,C03, ahp0.x,ahp1.x,ahp0.y,ahp1.y, bhi[ks][0][0], bhi[ks][0][1]);
                mma_bf16(C10,C11,C12,C13, ahp0.x,ahp1.x,ahp0.y,ahp1.y, bhi[ks][1][0], bhi[ks][1][1]);
                mma_bf16(C20,C21,C22,C23, ahp0.x,ahp1.x,ahp0.y,ahp1.y, bhi[ks][2][0], bhi[ks][2][1]);
                mma_bf16(C30,C31,C32,C33, ahp0.x,ahp1.x,ahp0.y,ahp1.y, bhi[ks][3][0], bhi[ks][3][1]);
                mma_bf16(C00,C01,C02,C03, ahp0.x,ahp1.x,ahp0.y,ahp1.y, blo[ks][0][0], blo[ks][0][1]);
                mma_bf16(C10,C11,C12,C13, ahp0.x,ahp1.x,ahp0.y,ahp1.y, blo[ks][1][0], blo[ks][1][1]);
                mma_bf16(C20,C21,C22,C23, ahp0.x,ahp1.x,ahp0.y,ahp1.y, blo[ks][2][0], blo[ks][2][1]);
                mma_bf16(C30,C31,C32,C33, ahp0.x,ahp1.x,ahp0.y,ahp1.y, blo[ks][3][0], blo[ks][3][1]);
                mma_bf16(C00,C01,C02,C03, alp0.x,alp1.x,alp0.y,alp1.y, bhi[ks][0][0], bhi[ks][0][1]);
                mma_bf16(C10,C11,C12,C13, alp0.x,alp1.x,alp0.y,alp1.y, bhi[ks][1][0], bhi[ks][1][1]);
                mma_bf16(C20,C21,C22,C23, alp0.x,alp1.x,alp0.y,alp1.y, bhi[ks][2][0], bhi[ks][2][1]);
                mma_bf16(C30,C31,C32,C33, alp0.x,alp1.x,alp0.y,alp1.y, bhi[ks][3][0], bhi[ks][3][1]);
            }

            // ---- scatter: perm cols, 4 red4/tile ----
            int dA = __shfl_sync(0xffffffffu, edc.y, gr);
            int dB = __shfl_sync(0xffffffffu, edc.y, gr + 8);
            float* pA = (float*)g_h2 + (size_t)dA * DIM + tig * 8;
            float* pB = (float*)g_h2 + (size_t)dB * DIM + tig * 8;
            red4(pA,     C00, C01, C10, C11);
            red4(pA + 4, C20, C21, C30, C31);
            red4(pB,     C02, C03, C12, C13);
            red4(pB + 4, C22, C23, C32, C33);

            edc = edn; edn = ed2; ed2 = ed3;
            bOff += 2048;
            if (bOff == 6144) bOff = 0;
        }
        e = runEnd;
    }
}

// Final: out[v] = relu(h2perm[v] + b2) @ W3 + b3; inverse perm read; resets
// h2 row and (block 0) the rel counters for the next graph replay.
__global__ void k_final(const float* __restrict__ W3, const float* __restrict__ b2,
                        const float* __restrict__ b3, float* __restrict__ out, int N) {
    __shared__ float sW[DIM * DIM];
    __shared__ float sb2[DIM];
    __shared__ float sb3[DIM];
    int t = threadIdx.x;
    for (int i = t; i < DIM * DIM; i += blockDim.x) sW[i] = W3[i];
    if (t < DIM) { sb2[t] = b2[t]; sb3[t] = b3[t]; }
    if (blockIdx.x == 0 && t < NRELS) { g_relHist[t] = 0; g_relCur[t] = 0; }
    __syncthreads();
    int lane = t & 31;
    int wpb = blockDim.x >> 5;
    int pos = ((lane & 7) >> 1) * 8 + (lane >> 3) * 2 + (lane & 1);
    float* h2 = (float*)g_h2;
    for (int v = blockIdx.x * wpb + (t >> 5); v < N; v += gridDim.x * wpb) {
        float h = fmaxf(h2[v * DIM + pos] + sb2[lane], 0.0f);
        h2[v * DIM + lane] = 0.0f;
        float acc = sb3[lane];
#pragma unroll
        for (int i = 0; i < DIM; i++) {
            float hi = __shfl_sync(0xffffffffu, h, i);
            acc += hi * sW[i * DIM + lane];
        }
        out[v * DIM + lane] = acc;
    }
}

// ---------------- launch ----------------
extern "C" void kernel_launch(void* const* d_in, const int* in_sizes, int n_in,
                              void* d_out, int out_size) {
    const int* src = (const int*)d_in[0];
    const int* dst = (const int*)d_in[1];
    const int* et  = (const int*)d_in[2];
    int base = (n_in > 3 && in_sizes[3] == 1) ? 4 : 3;
    const float* W1 = (const float*)d_in[base + 0];
    const float* b1 = (const float*)d_in[base + 1];
    const float* W2 = (const float*)d_in[base + 2];
    const float* b2 = (const float*)d_in[base + 3];
    const float* W3 = (const float*)d_in[base + 4];
    const float* b3 = (const float*)d_in[base + 5];

    int E = in_sizes[0];
    int N = out_size / DIM;
    float* out = (float*)d_out;

    int edgeBlocks4 = (E / 4 + 255) / 256 + 1;
    k_hist<<<edgeBlocks4, 256>>>(dst, et, E);          // launch 0
    k_scatter<<<edgeBlocks4, 256>>>(src, dst, et, E);  // launch 1

    int nodeBlocks = (N + 7) / 8;
    k_layer1<<<nodeBlocks, 256>>>(W1, b1, N);          // launch 2

    const int nWarps = 2960;   // 148 SMs x 5 blocks x 4 warps, one wave
    k_layer2<<<nWarps / 4, 128>>>(W2, E, nWarps);      // launch 3 (profiled slot)

    k_final<<<nodeBlocks, 256>>>(W3, b2, b3, out, N);  // launch 4
}

// round 16
// speedup vs baseline: 2.6009x; 1.0078x over previous
#include <cuda_runtime.h>

#define NRELS 19
#define CPAD  20
#define DIM   32
#define MAXN  100000
#define MAXE  1600000

typedef unsigned int u32;

// ---------------- static scratch (zero-init; consumers reset what they read
// so every graph replay starts pristine) ------------------------------------
static __device__ int4   g_cnt4[MAXN * (CPAD / 4)];   // (node,rel) counts
static __device__ u32    g_h1u[MAXN * DIM];           // h1, SPLIT bf16, fragment order
static __device__ float4 g_h2[MAXN * (DIM / 4)];      // layer-2 accumulator (perm cols)
static __device__ int2   g_edataR[(size_t)NRELS * MAXE]; // per-relation edge buckets
static __device__ int    g_relCur[NRELS];             // per-relation cursors (= counts)
static __device__ int    g_relOff[NRELS + 1];         // prefix offsets (k_scan)

// ---------------- helpers ----------------
__device__ __forceinline__ void red4(float* p, float a, float b, float c, float d) {
    asm volatile("red.global.add.v4.f32 [%0], {%1, %2, %3, %4};"
                 :: "l"(p), "f"(a), "f"(b), "f"(c), "f"(d) : "memory");
}
__device__ __forceinline__ u32 smem_u32(const void* p) {
    return (u32)__cvta_generic_to_shared(p);
}
__device__ __forceinline__ void cp_async16(u32 dst, const void* src, int srcsize) {
    asm volatile("cp.async.cg.shared.global [%0], [%1], 16, %2;"
                 :: "r"(dst), "l"(src), "r"(srcsize));
}
// unguarded variant for the steady-state loop (no src-size operand)
__device__ __forceinline__ void cp_async16u(u32 dst, const void* src) {
    asm volatile("cp.async.cg.shared.global [%0], [%1], 16;"
                 :: "r"(dst), "l"(src));
}
__device__ __forceinline__ void cp_commit() { asm volatile("cp.async.commit_group;"); }
__device__ __forceinline__ void cp_wait2()  { asm volatile("cp.async.wait_group 2;"); }
__device__ __forceinline__ void cp_wait0()  { asm volatile("cp.async.wait_group 0;"); }
__device__ __forceinline__ u32 bf16x2(float lo, float hi) {
    u32 r; asm("cvt.rn.bf16x2.f32 %0, %1, %2;" : "=r"(r) : "f"(hi), "f"(lo)); return r;
}
__device__ __forceinline__ u32 bf16x2_lo(float x, float y, u32 hi) {
    float lx = x - __uint_as_float(hi << 16);
    float ly = y - __uint_as_float(hi & 0xFFFF0000u);
    return bf16x2(lx, ly);
}
__device__ __forceinline__ void mma_bf16(float& c0, float& c1, float& c2, float& c3,
                                         u32 a0, u32 a1, u32 a2, u32 a3,
                                         u32 b0, u32 b1) {
    asm volatile("mma.sync.aligned.m16n8k16.row.col.f32.bf16.bf16.f32 "
                 "{%0,%1,%2,%3}, {%4,%5,%6,%7}, {%8,%9}, {%0,%1,%2,%3};"
                 : "+f"(c0), "+f"(c1), "+f"(c2), "+f"(c3)
                 : "r"(a0), "r"(a1), "r"(a2), "r"(a3), "r"(b0), "r"(b1));
}

// ---------------- kernels (order: scatcnt, layer1, scan, LAYER2, final) ----

// Fused hist+scatter single pass: per-(dst,rel) count atomics AND relation
// bucketing into per-relation arrays with block-aggregated global cursors.
__global__ void k_scatcnt(const int* __restrict__ src, const int* __restrict__ dst,
                          const int* __restrict__ et, int E) {
    __shared__ int shCnt[NRELS];
    __shared__ int shBase[NRELS];
    int t = threadIdx.x;
    if (t < NRELS) shCnt[t] = 0;
    __syncthreads();
    int* cnt = (int*)g_cnt4;
    int e0 = (blockIdx.x * blockDim.x + t) * 4;
    int r[4], s[4], d[4], lp[4];
    int n = 0;
    if (e0 + 3 < E) {
        int4 s4 = *(const int4*)&src[e0];
        int4 d4 = *(const int4*)&dst[e0];
        int4 r4 = *(const int4*)&et[e0];
        s[0]=s4.x; s[1]=s4.y; s[2]=s4.z; s[3]=s4.w;
        d[0]=d4.x; d[1]=d4.y; d[2]=d4.z; d[3]=d4.w;
        r[0]=r4.x; r[1]=r4.y; r[2]=r4.z; r[3]=r4.w;
        n = 4;
    } else {
        for (int e = e0; e < E; e++) { s[n]=src[e]; d[n]=dst[e]; r[n]=et[e]; n++; }
    }
    for (int k = 0; k < n; k++) {
        atomicAdd(&cnt[d[k] * CPAD + r[k]], 1);
        lp[k] = atomicAdd(&shCnt[r[k]], 1);
    }
    __syncthreads();
    if (t < NRELS) shBase[t] = atomicAdd(&g_relCur[t], shCnt[t]);
    __syncthreads();
    for (int k = 0; k < n; k++)
        g_edataR[(size_t)r[k] * MAXE + shBase[r[k]] + lp[k]] = make_int2(s[k], d[k]);
}

// Layer 1: h1 = relu(cnt @ W1 + b1) written as SPLIT bf16 in fragment order.
// RESETS cnt rows after reading.
__global__ void k_layer1(const float* __restrict__ W1, const float* __restrict__ b1, int N) {
    __shared__ float sW[NRELS * DIM];
    __shared__ float sb[DIM];
    int t = threadIdx.x;
    for (int i = t; i < NRELS * DIM; i += blockDim.x) sW[i] = W1[i];
    if (t < DIM) sb[t] = b1[t];
    __syncthreads();
    int lane = t & 31;
    int wpb = blockDim.x >> 5;
    int slot = lane & 15;
    int pr = ((slot >> 3) << 3) + ((slot & 7) >> 1) + ((slot & 1) << 2);
    for (int v = blockIdx.x * wpb + (t >> 5); v < N; v += gridDim.x * wpb) {
        int4* crow = &g_cnt4[v * (CPAD / 4)];
        int c[CPAD];
#pragma unroll
        for (int q = 0; q < CPAD / 4; q++) {
            int4 cc = __ldg(&crow[q]);
            c[q * 4 + 0] = cc.x; c[q * 4 + 1] = cc.y;
            c[q * 4 + 2] = cc.z; c[q * 4 + 3] = cc.w;
        }
        float acc = sb[lane];
#pragma unroll
        for (int r = 0; r < NRELS; r++)
            acc += (float)c[r] * sW[r * DIM + lane];
        float h = fmaxf(acc, 0.0f);
        float hx = __shfl_sync(0xffffffffu, h, 2 * pr);
        float hy = __shfl_sync(0xffffffffu, h, 2 * pr + 1);
        u32 hi = bf16x2(hx, hy);
        u32 val = (lane < 16) ? hi : bf16x2_lo(hx, hy, hi);
        g_h1u[v * DIM + (lane < 16 ? slot : 16 + slot)] = val;
        if (lane < CPAD / 4) crow[lane] = make_int4(0, 0, 0, 0);
    }
}

// 19-entry prefix scan of the relation counts.
__global__ void k_scan() {
    if (threadIdx.x == 0) {
        int s = 0;
        for (int r = 0; r < NRELS; r++) { g_relOff[r] = s; s += g_relCur[r]; }
        g_relOff[NRELS] = s;
    }
}

// Layer 2 (hot): bf16 tensor tiles, 16 edges/tile/warp, h1 pre-split.
// Round-16: STEADY-STATE loop (no bounds checks, constant-size cp.async,
// hoisted swizzle/address arithmetic) + guarded tail.  3-stage pipeline,
// natural 5 blocks/SM, perm-column red4 scatter.
__global__ void __launch_bounds__(128, 5) k_layer2(const float* __restrict__ W2,
                                                   int E, int nWarps) {
    __shared__ u32 shh[4][3][512];      // [warp][buf][16 rows x 32 u32] 24KB
    __shared__ int sOff[NRELS + 1];
    int t = threadIdx.x;
    if (t <= NRELS) sOff[t] = g_relOff[t];
    __syncthreads();
    int lane = t & 31;
    int warp = t >> 5;
    int gr   = lane >> 2;
    int tig  = lane & 3;
    int grow = lane >> 3;
    int gchk = lane & 7;
    bool lane16 = lane < 16;
    u32 shW = smem_u32(&shh[warp][0][0]);
    const char* sbase = (const char*)&shh[warp][0][0];
    const char* h1base = (const char*)g_h1u + gchk * 16;

    // hoisted gather destination offsets (row*128 + swizzled chunk)
    u32 rowOff[4];
#pragma unroll
    for (int i = 0; i < 4; i++) {
        int row = i * 4 + grow;
        rowOff[i] = row * 128 + ((gchk ^ (row & 7)) * 16);
    }
    // hoisted compute LDS offsets: ks in {0,1}, hi chunk ch=ks*2+(tig>>1), lo=ch+4
    int rem = (tig & 1) * 8;
    u32 offA0 = ((((tig >> 1))     ^ gr) * 16) + rem;
    u32 offB0 = ((((tig >> 1) + 4) ^ gr) * 16) + rem;
    u32 offA1 = (((2 + (tig >> 1))     ^ gr) * 16) + rem;
    u32 offB1 = (((2 + (tig >> 1) + 4) ^ gr) * 16) + rem;

    int gw = blockIdx.x * 4 + warp;
    if (gw >= nWarps) return;
    int e    = (int)(((long long)gw * E) / nWarps);
    int eEnd = (int)(((long long)(gw + 1) * E) / nWarps);

    int r = 0;
    while (e < eEnd) {
        while (sOff[r + 1] <= e) r++;
        int runEnd = min(eEnd, sOff[r + 1]);
        if (e >= runEnd) continue;
        const int2* ep = g_edataR + ((size_t)r * MAXE - (size_t)sOff[r]);

        // ---- W2[r] bf16 hi/lo fragments, register-resident ----
        const float* Wr = W2 + r * DIM * DIM;
        u32 bhi[2][4][2], blo[2][4][2];
#pragma unroll
        for (int ks = 0; ks < 2; ks++)
#pragma unroll
            for (int nb = 0; nb < 4; nb++) {
                int k0 = ks * 16 + 2 * tig, n0 = nb * 8 + gr;
                float w00 = __ldg(&Wr[k0 * DIM + n0]);
                float w01 = __ldg(&Wr[(k0 + 1) * DIM + n0]);
                float w10 = __ldg(&Wr[(k0 + 8) * DIM + n0]);
                float w11 = __ldg(&Wr[(k0 + 9) * DIM + n0]);
                u32 h0 = bf16x2(w00, w01);
                u32 h1 = bf16x2(w10, w11);
                bhi[ks][nb][0] = h0;
                bhi[ks][nb][1] = h1;
                blo[ks][nb][0] = bf16x2_lo(w00, w01, h0);
                blo[ks][nb][1] = bf16x2_lo(w10, w11, h1);
            }

        cp_wait0();
        __syncwarp();

        // ---- prolog: edata 3 tiles deep; gather tiles e, e+16 into bufs 0,1
        int2 edc = make_int2(0, 0), edn = make_int2(0, 0), ed2 = make_int2(0, 0);
        if (lane16 && e + lane < runEnd) edc = __ldg(&ep[e + lane]);
        if (lane16 && e + 16 + lane < runEnd) edn = __ldg(&ep[e + 16 + lane]);
        if (lane16 && e + 32 + lane < runEnd) ed2 = __ldg(&ep[e + 32 + lane]);
#pragma unroll
        for (int i = 0; i < 4; i++) {
            int sk = __shfl_sync(0xffffffffu, edc.x, i * 4 + grow);
            cp_async16(shW + rowOff[i], h1base + (size_t)sk * 128,
                       (e + i * 4 + grow < runEnd) ? 16 : 0);
        }
        cp_commit();
#pragma unroll
        for (int i = 0; i < 4; i++) {
            int sk = __shfl_sync(0xffffffffu, edn.x, i * 4 + grow);
            cp_async16(shW + 2048 + rowOff[i], h1base + (size_t)sk * 128,
                       (e + 16 + i * 4 + grow < runEnd) ? 16 : 0);
        }
        cp_commit();

        u32 bOff = 0;
        int c = e;

        // ================= steady-state: no bounds checks =================
        for (; c + 64 <= runEnd; c += 16) {
            int2 ed3 = make_int2(0, 0);
            if (lane16) ed3 = __ldg(&ep[c + 48 + lane]);
            u32 gOff = bOff + 4096;
            if (gOff >= 6144) gOff -= 6144;
            u32 gbase = shW + gOff;
#pragma unroll
            for (int i = 0; i < 4; i++) {
                int sk = __shfl_sync(0xffffffffu, ed2.x, i * 4 + grow);
                cp_async16u(gbase + rowOff[i], h1base + (size_t)sk * 128);
            }
            cp_commit();
            cp_wait2();
            __syncwarp();

            float C00=0,C01=0,C02=0,C03=0, C10=0,C11=0,C12=0,C13=0;
            float C20=0,C21=0,C22=0,C23=0, C30=0,C31=0,C32=0,C33=0;
            const char* rp0 = sbase + bOff + gr * 128;
            const char* rp1 = rp0 + 1024;
            {
                uint2 ah0 = *(const uint2*)(rp0 + offA0);
                uint2 ah1 = *(const uint2*)(rp1 + offA0);
                uint2 al0 = *(const uint2*)(rp0 + offB0);
                uint2 al1 = *(const uint2*)(rp1 + offB0);
                mma_bf16(C00,C01,C02,C03, ah0.x,ah1.x,ah0.y,ah1.y, bhi[0][0][0], bhi[0][0][1]);
                mma_bf16(C10,C11,C12,C13, ah0.x,ah1.x,ah0.y,ah1.y, bhi[0][1][0], bhi[0][1][1]);
                mma_bf16(C20,C21,C22,C23, ah0.x,ah1.x,ah0.y,ah1.y, bhi[0][2][0], bhi[0][2][1]);
                mma_bf16(C30,C31,C32,C33, ah0.x,ah1.x,ah0.y,ah1.y, bhi[0][3][0], bhi[0][3][1]);
                mma_bf16(C00,C01,C02,C03, ah0.x,ah1.x,ah0.y,ah1.y, blo[0][0][0], blo[0][0][1]);
                mma_bf16(C10,C11,C12,C13, ah0.x,ah1.x,ah0.y,ah1.y, blo[0][1][0], blo[0][1][1]);
                mma_bf16(C20,C21,C22,C23, ah0.x,ah1.x,ah0.y,ah1.y, blo[0][2][0], blo[0][2][1]);
                mma_bf16(C30,C31,C32,C33, ah0.x,ah1.x,ah0.y,ah1.y, blo[0][3][0], blo[0][3][1]);
                mma_bf16(C00,C01,C02,C03, al0.x,al1.x,al0.y,al1.y, bhi[0][0][0], bhi[0][0][1]);
                mma_bf16(C10,C11,C12,C13, al0.x,al1.x,al0.y,al1.y, bhi[0][1][0], bhi[0][1][1]);
                mma_bf16(C20,C21,C22,C23, al0.x,al1.x,al0.y,al1.y, bhi[0][2][0], bhi[0][2][1]);
                mma_bf16(C30,C31,C32,C33, al0.x,al1.x,al0.y,al1.y, bhi[0][3][0], bhi[0][3][1]);
            }
            {
                uint2 ah0 = *(const uint2*)(rp0 + offA1);
                uint2 ah1 = *(const uint2*)(rp1 + offA1);
                uint2 al0 = *(const uint2*)(rp0 + offB1);
                uint2 al1 = *(const uint2*)(rp1 + offB1);
                mma_bf16(C00,C01,C02,C03, ah0.x,ah1.x,ah0.y,ah1.y, bhi[1][0][0], bhi[1][0][1]);
                mma_bf16(C10,C11,C12,C13, ah0.x,ah1.x,ah0.y,ah1.y, bhi[1][1][0], bhi[1][1][1]);
                mma_bf16(C20,C21,C22,C23, ah0.x,ah1.x,ah0.y,ah1.y, bhi[1][2][0], bhi[1][2][1]);
                mma_bf16(C30,C31,C32,C33, ah0.x,ah1.x,ah0.y,ah1.y, bhi[1][3][0], bhi[1][3][1]);
                mma_bf16(C00,C01,C02,C03, ah0.x,ah1.x,ah0.y,ah1.y, blo[1][0][0], blo[1][0][1]);
                mma_bf16(C10,C11,C12,C13, ah0.x,ah1.x,ah0.y,ah1.y, blo[1][1][0], blo[1][1][1]);
                mma_bf16(C20,C21,C22,C23, ah0.x,ah1.x,ah0.y,ah1.y, blo[1][2][0], blo[1][2][1]);
                mma_bf16(C30,C31,C32,C33, ah0.x,ah1.x,ah0.y,ah1.y, blo[1][3][0], blo[1][3][1]);
                mma_bf16(C00,C01,C02,C03, al0.x,al1.x,al0.y,al1.y, bhi[1][0][0], bhi[1][0][1]);
                mma_bf16(C10,C11,C12,C13, al0.x,al1.x,al0.y,al1.y, bhi[1][1][0], bhi[1][1][1]);
                mma_bf16(C20,C21,C22,C23, al0.x,al1.x,al0.y,al1.y, bhi[1][2][0], bhi[1][2][1]);
                mma_bf16(C30,C31,C32,C33, al0.x,al1.x,al0.y,al1.y, bhi[1][3][0], bhi[1][3][1]);
            }

            int dA = __shfl_sync(0xffffffffu, edc.y, gr);
            int dB = __shfl_sync(0xffffffffu, edc.y, gr + 8);
            float* pA = (float*)g_h2 + (size_t)dA * DIM + tig * 8;
            float* pB = (float*)g_h2 + (size_t)dB * DIM + tig * 8;
            red4(pA,     C00, C01, C10, C11);
            red4(pA + 4, C20, C21, C30, C31);
            red4(pB,     C02, C03, C12, C13);
            red4(pB + 4, C22, C23, C32, C33);

            edc = edn; edn = ed2; ed2 = ed3;
            bOff += 2048;
            if (bOff == 6144) bOff = 0;
        }

        // ================= guarded tail =================
        for (; c < runEnd; c += 16) {
            int2 ed3 = make_int2(0, 0);
            if (lane16 && c + 48 + lane < runEnd) ed3 = __ldg(&ep[c + 48 + lane]);
            u32 gOff = bOff + 4096;
            if (gOff >= 6144) gOff -= 6144;
            u32 gbase = shW + gOff;
#pragma unroll
            for (int i = 0; i < 4; i++) {
                int sk = __shfl_sync(0xffffffffu, ed2.x, i * 4 + grow);
                cp_async16(gbase + rowOff[i], h1base + (size_t)sk * 128,
                           (c + 32 + i * 4 + grow < runEnd) ? 16 : 0);
            }
            cp_commit();
            cp_wait2();
            __syncwarp();

            float C00=0,C01=0,C02=0,C03=0, C10=0,C11=0,C12=0,C13=0;
            float C20=0,C21=0,C22=0,C23=0, C30=0,C31=0,C32=0,C33=0;
            const char* rp0 = sbase + bOff + gr * 128;
            const char* rp1 = rp0 + 1024;
#pragma unroll
            for (int ks = 0; ks < 2; ks++) {
                u32 oA = ks ? offA1 : offA0;
                u32 oB = ks ? offB1 : offB0;
                uint2 ah0 = *(const uint2*)(rp0 + oA);
                uint2 ah1 = *(const uint2*)(rp1 + oA);
                uint2 al0 = *(const uint2*)(rp0 + oB);
                uint2 al1 = *(const uint2*)(rp1 + oB);
                mma_bf16(C00,C01,C02,C03, ah0.x,ah1.x,ah0.y,ah1.y, bhi[ks][0][0], bhi[ks][0][1]);
                mma_bf16(C10,C11,C12,C13, ah0.x,ah1.x,ah0.y,ah1.y, bhi[ks][1][0], bhi[ks][1][1]);
                mma_bf16(C20,C21,C22,C23, ah0.x,ah1.x,ah0.y,ah1.y, bhi[ks][2][0], bhi[ks][2][1]);
                mma_bf16(C30,C31,C32,C33, ah0.x,ah1.x,ah0.y,ah1.y, bhi[ks][3][0], bhi[ks][3][1]);
                mma_bf16(C00,C01,C02,C03, ah0.x,ah1.x,ah0.y,ah1.y, blo[ks][0][0], blo[ks][0][1]);
                mma_bf16(C10,C11,C12,C13, ah0.x,ah1.x,ah0.y,ah1.y, blo[ks][1][0], blo[ks][1][1]);
                mma_bf16(C20,C21,C22,C23, ah0.x,ah1.x,ah0.y,ah1.y, blo[ks][2][0], blo[ks][2][1]);
                mma_bf16(C30,C31,C32,C33, ah0.x,ah1.x,ah0.y,ah1.y, blo[ks][3][0], blo[ks][3][1]);
                mma_bf16(C00,C01,C02,C03, al0.x,al1.x,al0.y,al1.y, bhi[ks][0][0], bhi[ks][0][1]);
                mma_bf16(C10,C11,C12,C13, al0.x,al1.x,al0.y,al1.y, bhi[ks][1][0], bhi[ks][1][1]);
                mma_bf16(C20,C21,C22,C23, al0.x,al1.x,al0.y,al1.y, bhi[ks][2][0], bhi[ks][2][1]);
                mma_bf16(C30,C31,C32,C33, al0.x,al1.x,al0.y,al1.y, bhi[ks][3][0], bhi[ks][3][1]);
            }

            int dA = __shfl_sync(0xffffffffu, edc.y, gr);
            int dB = __shfl_sync(0xffffffffu, edc.y, gr + 8);
            float* pA = (float*)g_h2 + (size_t)dA * DIM + tig * 8;
            float* pB = (float*)g_h2 + (size_t)dB * DIM + tig * 8;
            red4(pA,     C00, C01, C10, C11);
            red4(pA + 4, C20, C21, C30, C31);
            red4(pB,     C02, C03, C12, C13);
            red4(pB + 4, C22, C23, C32, C33);

            edc = edn; edn = ed2; ed2 = ed3;
            bOff += 2048;
            if (bOff == 6144) bOff = 0;
        }
        e = runEnd;
    }
}

// Final: out[v] = relu(h2perm[v] + b2) @ W3 + b3; inverse perm read; resets
// h2 row and (block 0) the relation cursors for the next graph replay.
__global__ void k_final(const float* __restrict__ W3, const float* __restrict__ b2,
                        const float* __restrict__ b3, float* __restrict__ out, int N) {
    __shared__ float sW[DIM * DIM];
    __shared__ float sb2[DIM];
    __shared__ float sb3[DIM];
    int t = threadIdx.x;
    for (int i = t; i < DIM * DIM; i += blockDim.x) sW[i] = W3[i];
    if (t < DIM) { sb2[t] = b2[t]; sb3[t] = b3[t]; }
    if (blockIdx.x == 0 && t < NRELS) g_relCur[t] = 0;
    __syncthreads();
    int lane = t & 31;
    int wpb = blockDim.x >> 5;
    int pos = ((lane & 7) >> 1) * 8 + (lane >> 3) * 2 + (lane & 1);
    float* h2 = (float*)g_h2;
    for (int v = blockIdx.x * wpb + (t >> 5); v < N; v += gridDim.x * wpb) {
        float h = fmaxf(h2[v * DIM + pos] + sb2[lane], 0.0f);
        h2[v * DIM + lane] = 0.0f;
        float acc = sb3[lane];
#pragma unroll
        for (int i = 0; i < DIM; i++) {
            float hi = __shfl_sync(0xffffffffu, h, i);
            acc += hi * sW[i * DIM + lane];
        }
        out[v * DIM + lane] = acc;
    }
}

// ---------------- launch ----------------
extern "C" void kernel_launch(void* const* d_in, const int* in_sizes, int n_in,
                              void* d_out, int out_size) {
    const int* src = (const int*)d_in[0];
    const int* dst = (const int*)d_in[1];
    const int* et  = (const int*)d_in[2];
    int base = (n_in > 3 && in_sizes[3] == 1) ? 4 : 3;
    const float* W1 = (const float*)d_in[base + 0];
    const float* b1 = (const float*)d_in[base + 1];
    const float* W2 = (const float*)d_in[base + 2];
    const float* b2 = (const float*)d_in[base + 3];
    const float* W3 = (const float*)d_in[base + 4];
    const float* b3 = (const float*)d_in[base + 5];

    int E = in_sizes[0];
    int N = out_size / DIM;
    float* out = (float*)d_out;

    int edgeBlocks4 = (E / 4 + 255) / 256 + 1;
    k_scatcnt<<<edgeBlocks4, 256>>>(src, dst, et, E);  // launch 0 (hist fused in)

    int nodeBlocks = (N + 7) / 8;
    k_layer1<<<nodeBlocks, 256>>>(W1, b1, N);          // launch 1

    k_scan<<<1, 32>>>();                               // launch 2

    const int nWarps = 2960;   // 148 SMs x 5 blocks x 4 warps, one wave
    k_layer2<<<nWarps / 4, 128>>>(W2, E, nWarps);      // launch 3 (profiled slot)

    k_final<<<nodeBlocks, 256>>>(W3, b2, b3, out, N);  // launch 4
}

// round 17
// speedup vs baseline: 2.6102x; 1.0036x over previous
#include <cuda_runtime.h>

#define NRELS 19
#define CPAD  20
#define DIM   32
#define MAXN  100000
#define MAXE  1600000

typedef unsigned int u32;

// ---------------- static scratch (zero-init; consumers reset what they read
// so every graph replay starts pristine) ------------------------------------
static __device__ int4   g_cnt4[MAXN * (CPAD / 4)];   // (node,rel) counts
static __device__ u32    g_h1u[MAXN * DIM];           // h1, SPLIT bf16, fragment order
static __device__ float4 g_h2[MAXN * (DIM / 4)];      // layer-2 accumulator (perm cols)
static __device__ int2   g_edataR[(size_t)NRELS * MAXE]; // per-relation edge buckets
static __device__ int    g_relCur[NRELS];             // per-relation cursors (= counts)
static __device__ int    g_relOff[NRELS + 1];         // prefix offsets (k_scan)

// ---------------- helpers ----------------
__device__ __forceinline__ void red4(float* p, float a, float b, float c, float d) {
    asm volatile("red.global.add.v4.f32 [%0], {%1, %2, %3, %4};"
                 :: "l"(p), "f"(a), "f"(b), "f"(c), "f"(d) : "memory");
}
__device__ __forceinline__ u32 smem_u32(const void* p) {
    return (u32)__cvta_generic_to_shared(p);
}
__device__ __forceinline__ void cp_async16(u32 dst, const void* src, int srcsize) {
    asm volatile("cp.async.cg.shared.global [%0], [%1], 16, %2;"
                 :: "r"(dst), "l"(src), "r"(srcsize));
}
__device__ __forceinline__ void cp_commit() { asm volatile("cp.async.commit_group;"); }
__device__ __forceinline__ void cp_wait2()  { asm volatile("cp.async.wait_group 2;"); }
__device__ __forceinline__ void cp_wait0()  { asm volatile("cp.async.wait_group 0;"); }
__device__ __forceinline__ u32 bf16x2(float lo, float hi) {
    u32 r; asm("cvt.rn.bf16x2.f32 %0, %1, %2;" : "=r"(r) : "f"(hi), "f"(lo)); return r;
}
__device__ __forceinline__ u32 bf16x2_lo(float x, float y, u32 hi) {
    float lx = x - __uint_as_float(hi << 16);
    float ly = y - __uint_as_float(hi & 0xFFFF0000u);
    return bf16x2(lx, ly);
}
__device__ __forceinline__ void mma_bf16(float& c0, float& c1, float& c2, float& c3,
                                         u32 a0, u32 a1, u32 a2, u32 a3,
                                         u32 b0, u32 b1) {
    asm volatile("mma.sync.aligned.m16n8k16.row.col.f32.bf16.bf16.f32 "
                 "{%0,%1,%2,%3}, {%4,%5,%6,%7}, {%8,%9}, {%0,%1,%2,%3};"
                 : "+f"(c0), "+f"(c1), "+f"(c2), "+f"(c3)
                 : "r"(a0), "r"(a1), "r"(a2), "r"(a3), "r"(b0), "r"(b1));
}

// ---------------- kernels (order: scatcnt, layer1, scan, LAYER2, final) ----

// Fused hist+scatter: per-(dst,rel) count atomics AND relation bucketing.
// Shared-counter atomics are WARP-AGGREGATED via match_any (one ATOMS per
// distinct relation per round instead of one per lane).
__global__ void k_scatcnt(const int* __restrict__ src, const int* __restrict__ dst,
                          const int* __restrict__ et, int E) {
    __shared__ int shCnt[NRELS];
    __shared__ int shBase[NRELS];
    int t = threadIdx.x;
    int lane = t & 31;
    if (t < NRELS) shCnt[t] = 0;
    __syncthreads();
    int* cnt = (int*)g_cnt4;
    int e0 = (blockIdx.x * blockDim.x + t) * 4;
    int r[4], s[4], d[4], lp[4];
    int n = 0;
    // warp-uniform "all 4 edges valid for every lane in this warp"
    bool fullw = ((blockIdx.x * blockDim.x + (t | 31)) * 4 + 3) < E;
    if (fullw) {
        int4 s4 = *(const int4*)&src[e0];
        int4 d4 = *(const int4*)&dst[e0];
        int4 r4 = *(const int4*)&et[e0];
        s[0]=s4.x; s[1]=s4.y; s[2]=s4.z; s[3]=s4.w;
        d[0]=d4.x; d[1]=d4.y; d[2]=d4.z; d[3]=d4.w;
        r[0]=r4.x; r[1]=r4.y; r[2]=r4.z; r[3]=r4.w;
        n = 4;
#pragma unroll
        for (int k = 0; k < 4; k++) {
            atomicAdd(&cnt[d[k] * CPAD + r[k]], 1);
            u32 mk = __match_any_sync(0xffffffffu, r[k]);
            int ldr = __ffs(mk) - 1;
            int pfx = __popc(mk & ((1u << lane) - 1));
            int base = 0;
            if (lane == ldr) base = atomicAdd(&shCnt[r[k]], __popc(mk));
            base = __shfl_sync(0xffffffffu, base, ldr);
            lp[k] = base + pfx;
        }
    } else {
        for (int e = e0; e < E && n < 4; e++) { s[n]=src[e]; d[n]=dst[e]; r[n]=et[e]; n++; }
        for (int k = 0; k < n; k++) {
            atomicAdd(&cnt[d[k] * CPAD + r[k]], 1);
            lp[k] = atomicAdd(&shCnt[r[k]], 1);
        }
    }
    __syncthreads();
    if (t < NRELS) shBase[t] = atomicAdd(&g_relCur[t], shCnt[t]);
    __syncthreads();
    for (int k = 0; k < n; k++)
        g_edataR[(size_t)r[k] * MAXE + shBase[r[k]] + lp[k]] = make_int2(s[k], d[k]);
}

// Layer 1: h1 = relu(cnt @ W1 + b1) written as SPLIT bf16 in fragment order.
// RESETS cnt rows after reading.
__global__ void k_layer1(const float* __restrict__ W1, const float* __restrict__ b1, int N) {
    __shared__ float sW[NRELS * DIM];
    __shared__ float sb[DIM];
    int t = threadIdx.x;
    for (int i = t; i < NRELS * DIM; i += blockDim.x) sW[i] = W1[i];
    if (t < DIM) sb[t] = b1[t];
    __syncthreads();
    int lane = t & 31;
    int wpb = blockDim.x >> 5;
    int slot = lane & 15;
    int pr = ((slot >> 3) << 3) + ((slot & 7) >> 1) + ((slot & 1) << 2);
    for (int v = blockIdx.x * wpb + (t >> 5); v < N; v += gridDim.x * wpb) {
        int4* crow = &g_cnt4[v * (CPAD / 4)];
        int c[CPAD];
#pragma unroll
        for (int q = 0; q < CPAD / 4; q++) {
            int4 cc = __ldg(&crow[q]);
            c[q * 4 + 0] = cc.x; c[q * 4 + 1] = cc.y;
            c[q * 4 + 2] = cc.z; c[q * 4 + 3] = cc.w;
        }
        float acc = sb[lane];
#pragma unroll
        for (int r = 0; r < NRELS; r++)
            acc += (float)c[r] * sW[r * DIM + lane];
        float h = fmaxf(acc, 0.0f);
        float hx = __shfl_sync(0xffffffffu, h, 2 * pr);
        float hy = __shfl_sync(0xffffffffu, h, 2 * pr + 1);
        u32 hi = bf16x2(hx, hy);
        u32 val = (lane < 16) ? hi : bf16x2_lo(hx, hy, hi);
        g_h1u[v * DIM + (lane < 16 ? slot : 16 + slot)] = val;
        if (lane < CPAD / 4) crow[lane] = make_int4(0, 0, 0, 0);
    }
}

// 19-entry prefix scan of the relation counts.
__global__ void k_scan() {
    if (threadIdx.x == 0) {
        int s = 0;
        for (int r = 0; r < NRELS; r++) { g_relOff[r] = s; s += g_relCur[r]; }
        g_relOff[NRELS] = s;
    }
}

// Layer 2 (hot): bf16 tensor tiles, 16 edges/tile/warp, h1 pre-split
// (round-15 body — the steady-state peel measured slightly negative).
// 3-stage cp.async pipeline, natural 5 blocks/SM, perm-column red4 scatter.
__global__ void __launch_bounds__(128, 5) k_layer2(const float* __restrict__ W2,
                                                   int E, int nWarps) {
    __shared__ u32 shh[4][3][512];      // [warp][buf][16 rows x 32 u32] 24KB
    __shared__ int sOff[NRELS + 1];
    int t = threadIdx.x;
    if (t <= NRELS) sOff[t] = g_relOff[t];
    __syncthreads();
    int lane = t & 31;
    int warp = t >> 5;
    int gr   = lane >> 2;
    int tig  = lane & 3;
    int grow = lane >> 3;
    int gchk = lane & 7;
    bool lane16 = lane < 16;
    u32 shW = smem_u32(&shh[warp][0][0]);
    const char* sbase = (const char*)&shh[warp][0][0];
    const char* h1base = (const char*)g_h1u + gchk * 16;

    u32 rowOff[4];
#pragma unroll
    for (int i = 0; i < 4; i++) {
        int row = i * 4 + grow;
        rowOff[i] = row * 128 + ((gchk ^ (row & 7)) * 16);
    }
    int rem = (tig & 1) * 8;
    u32 offA0 = ((((tig >> 1))     ^ gr) * 16) + rem;
    u32 offB0 = ((((tig >> 1) + 4) ^ gr) * 16) + rem;
    u32 offA1 = (((2 + (tig >> 1))     ^ gr) * 16) + rem;
    u32 offB1 = (((2 + (tig >> 1) + 4) ^ gr) * 16) + rem;

    int gw = blockIdx.x * 4 + warp;
    if (gw >= nWarps) return;
    int e    = (int)(((long long)gw * E) / nWarps);
    int eEnd = (int)(((long long)(gw + 1) * E) / nWarps);

    int r = 0;
    while (e < eEnd) {
        while (sOff[r + 1] <= e) r++;
        int runEnd = min(eEnd, sOff[r + 1]);
        if (e >= runEnd) continue;
        const int2* ep = g_edataR + ((size_t)r * MAXE - (size_t)sOff[r]);

        // ---- W2[r] bf16 hi/lo fragments, register-resident ----
        const float* Wr = W2 + r * DIM * DIM;
        u32 bhi[2][4][2], blo[2][4][2];
#pragma unroll
        for (int ks = 0; ks < 2; ks++)
#pragma unroll
            for (int nb = 0; nb < 4; nb++) {
                int k0 = ks * 16 + 2 * tig, n0 = nb * 8 + gr;
                float w00 = __ldg(&Wr[k0 * DIM + n0]);
                float w01 = __ldg(&Wr[(k0 + 1) * DIM + n0]);
                float w10 = __ldg(&Wr[(k0 + 8) * DIM + n0]);
                float w11 = __ldg(&Wr[(k0 + 9) * DIM + n0]);
                u32 h0 = bf16x2(w00, w01);
                u32 h1 = bf16x2(w10, w11);
                bhi[ks][nb][0] = h0;
                bhi[ks][nb][1] = h1;
                blo[ks][nb][0] = bf16x2_lo(w00, w01, h0);
                blo[ks][nb][1] = bf16x2_lo(w10, w11, h1);
            }

        cp_wait0();
        __syncwarp();

        // ---- prolog: edata 3 tiles deep; gather tiles e, e+16 into bufs 0,1
        int2 edc = make_int2(0, 0), edn = make_int2(0, 0), ed2 = make_int2(0, 0);
        if (lane16 && e + lane < runEnd) edc = __ldg(&ep[e + lane]);
        if (lane16 && e + 16 + lane < runEnd) edn = __ldg(&ep[e + 16 + lane]);
        if (lane16 && e + 32 + lane < runEnd) ed2 = __ldg(&ep[e + 32 + lane]);
#pragma unroll
        for (int i = 0; i < 4; i++) {
            int sk = __shfl_sync(0xffffffffu, edc.x, i * 4 + grow);
            cp_async16(shW + rowOff[i], h1base + (size_t)sk * 128,
                       (e + i * 4 + grow < runEnd) ? 16 : 0);
        }
        cp_commit();
#pragma unroll
        for (int i = 0; i < 4; i++) {
            int sk = __shfl_sync(0xffffffffu, edn.x, i * 4 + grow);
            cp_async16(shW + 2048 + rowOff[i], h1base + (size_t)sk * 128,
                       (e + 16 + i * 4 + grow < runEnd) ? 16 : 0);
        }
        cp_commit();

        u32 bOff = 0;
        for (int c = e; c < runEnd; c += 16) {
            int2 ed3 = make_int2(0, 0);
            if (lane16 && c + 48 + lane < runEnd) ed3 = __ldg(&ep[c + 48 + lane]);
            u32 gOff = bOff + 4096;
            if (gOff >= 6144) gOff -= 6144;
            u32 gbase = shW + gOff;
#pragma unroll
            for (int i = 0; i < 4; i++) {
                int sk = __shfl_sync(0xffffffffu, ed2.x, i * 4 + grow);
                cp_async16(gbase + rowOff[i], h1base + (size_t)sk * 128,
                           (c + 32 + i * 4 + grow < runEnd) ? 16 : 0);
            }
            cp_commit();
            cp_wait2();
            __syncwarp();

            float C00=0,C01=0,C02=0,C03=0, C10=0,C11=0,C12=0,C13=0;
            float C20=0,C21=0,C22=0,C23=0, C30=0,C31=0,C32=0,C33=0;
            const char* rp0 = sbase + bOff + gr * 128;
            const char* rp1 = rp0 + 1024;
#pragma unroll
            for (int ks = 0; ks < 2; ks++) {
                u32 oA = ks ? offA1 : offA0;
                u32 oB = ks ? offB1 : offB0;
                uint2 ah0 = *(const uint2*)(rp0 + oA);
                uint2 ah1 = *(const uint2*)(rp1 + oA);
                uint2 al0 = *(const uint2*)(rp0 + oB);
                uint2 al1 = *(const uint2*)(rp1 + oB);
                mma_bf16(C00,C01,C02,C03, ah0.x,ah1.x,ah0.y,ah1.y, bhi[ks][0][0], bhi[ks][0][1]);
                mma_bf16(C10,C11,C12,C13, ah0.x,ah1.x,ah0.y,ah1.y, bhi[ks][1][0], bhi[ks][1][1]);
                mma_bf16(C20,C21,C22,C23, ah0.x,ah1.x,ah0.y,ah1.y, bhi[ks][2][0], bhi[ks][2][1]);
                mma_bf16(C30,C31,C32,C33, ah0.x,ah1.x,ah0.y,ah1.y, bhi[ks][3][0], bhi[ks][3][1]);
                mma_bf16(C00,C01,C02,C03, ah0.x,ah1.x,ah0.y,ah1.y, blo[ks][0][0], blo[ks][0][1]);
                mma_bf16(C10,C11,C12,C13, ah0.x,ah1.x,ah0.y,ah1.y, blo[ks][1][0], blo[ks][1][1]);
                mma_bf16(C20,C21,C22,C23, ah0.x,ah1.x,ah0.y,ah1.y, blo[ks][2][0], blo[ks][2][1]);
                mma_bf16(C30,C31,C32,C33, ah0.x,ah1.x,ah0.y,ah1.y, blo[ks][3][0], blo[ks][3][1]);
                mma_bf16(C00,C01,C02,C03, al0.x,al1.x,al0.y,al1.y, bhi[ks][0][0], bhi[ks][0][1]);
                mma_bf16(C10,C11,C12,C13, al0.x,al1.x,al0.y,al1.y, bhi[ks][1][0], bhi[ks][1][1]);
                mma_bf16(C20,C21,C22,C23, al0.x,al1.x,al0.y,al1.y, bhi[ks][2][0], bhi[ks][2][1]);
                mma_bf16(C30,C31,C32,C33, al0.x,al1.x,al0.y,al1.y, bhi[ks][3][0], bhi[ks][3][1]);
            }

            int dA = __shfl_sync(0xffffffffu, edc.y, gr);
            int dB = __shfl_sync(0xffffffffu, edc.y, gr + 8);
            float* pA = (float*)g_h2 + (size_t)dA * DIM + tig * 8;
            float* pB = (float*)g_h2 + (size_t)dB * DIM + tig * 8;
            red4(pA,     C00, C01, C10, C11);
            red4(pA + 4, C20, C21, C30, C31);
            red4(pB,     C02, C03, C12, C13);
            red4(pB + 4, C22, C23, C32, C33);

            edc = edn; edn = ed2; ed2 = ed3;
            bOff += 2048;
            if (bOff == 6144) bOff = 0;
        }
        e = runEnd;
    }
}

// Final: out[v] = relu(h2perm[v] + b2) @ W3 + b3; inverse perm read; resets
// h2 row and (block 0) the relation cursors for the next graph replay.
__global__ void k_final(const float* __restrict__ W3, const float* __restrict__ b2,
                        const float* __restrict__ b3, float* __restrict__ out, int N) {
    __shared__ float sW[DIM * DIM];
    __shared__ float sb2[DIM];
    __shared__ float sb3[DIM];
    int t = threadIdx.x;
    for (int i = t; i < DIM * DIM; i += blockDim.x) sW[i] = W3[i];
    if (t < DIM) { sb2[t] = b2[t]; sb3[t] = b3[t]; }
    if (blockIdx.x == 0 && t < NRELS) g_relCur[t] = 0;
    __syncthreads();
    int lane = t & 31;
    int wpb = blockDim.x >> 5;
    int pos = ((lane & 7) >> 1) * 8 + (lane >> 3) * 2 + (lane & 1);
    float* h2 = (float*)g_h2;
    for (int v = blockIdx.x * wpb + (t >> 5); v < N; v += gridDim.x * wpb) {
        float h = fmaxf(h2[v * DIM + pos] + sb2[lane], 0.0f);
        h2[v * DIM + lane] = 0.0f;
        float acc = sb3[lane];
#pragma unroll
        for (int i = 0; i < DIM; i++) {
            float hi = __shfl_sync(0xffffffffu, h, i);
            acc += hi * sW[i * DIM + lane];
        }
        out[v * DIM + lane] = acc;
    }
}

// ---------------- launch ----------------
extern "C" void kernel_launch(void* const* d_in, const int* in_sizes, int n_in,
                              void* d_out, int out_size) {
    const int* src = (const int*)d_in[0];
    const int* dst = (const int*)d_in[1];
    const int* et  = (const int*)d_in[2];
    int base = (n_in > 3 && in_sizes[3] == 1) ? 4 : 3;
    const float* W1 = (const float*)d_in[base + 0];
    const float* b1 = (const float*)d_in[base + 1];
    const float* W2 = (const float*)d_in[base + 2];
    const float* b2 = (const float*)d_in[base + 3];
    const float* W3 = (const float*)d_in[base + 4];
    const float* b3 = (const float*)d_in[base + 5];

    int E = in_sizes[0];
    int N = out_size / DIM;
    float* out = (float*)d_out;

    int edgeBlocks4 = (E / 4 + 255) / 256 + 1;
    k_scatcnt<<<edgeBlocks4, 256>>>(src, dst, et, E);  // launch 0 (hist fused in)

    int nodeBlocks = (N + 7) / 8;
    k_layer1<<<nodeBlocks, 256>>>(W1, b1, N);          // launch 1

    k_scan<<<1, 32>>>();                               // launch 2

    const int nWarps = 2960;   // 148 SMs x 5 blocks x 4 warps, one wave
    k_layer2<<<nWarps / 4, 128>>>(W2, E, nWarps);      // launch 3 (profiled slot)

    k_final<<<nodeBlocks, 256>>>(W3, b2, b3, out, N);  // launch 4
}